// round 1
// baseline (speedup 1.0000x reference)
#include <cuda_runtime.h>

#define C 32
#define EPS_BN 1e-5f

// W layout: [3 branches][3 taps][32 in][32 out] -> a*3072 + t*1024 + i*32 + j
__global__ __launch_bounds__(256) void recon_kernel(
    const float* __restrict__ f,
    const int*   __restrict__ nbr_prev,
    const int*   __restrict__ nbr_next,
    const float* __restrict__ W,
    const float* __restrict__ gamma,
    const float* __restrict__ beta,
    const float* __restrict__ mean,
    const float* __restrict__ var,
    float* __restrict__ out, int n)
{
    __shared__ float Wsm[9 * 1024];   // BN-folded weights
    __shared__ float Bsm[3][32];      // BN-folded bias

    const int tid = threadIdx.x;

    // Fold BN scale into weights: W'[a,t,i,j] = W * gamma[a,j]*rsqrt(var[a,j]+eps)
    for (int idx = tid; idx < 9 * 1024; idx += blockDim.x) {
        int a = idx / 3072;
        int j = idx & 31;
        float sc = gamma[a * 32 + j] * rsqrtf(var[a * 32 + j] + EPS_BN);
        Wsm[idx] = W[idx] * sc;
    }
    if (tid < 96) {
        int a = tid >> 5, j = tid & 31;
        float sc = gamma[tid] * rsqrtf(var[tid] + EPS_BN);
        Bsm[a][j] = beta[tid] - mean[tid] * sc;
    }
    __syncthreads();

    const int lane   = tid & 31;
    const int warp   = tid >> 5;
    const int gwarp  = blockIdx.x * (blockDim.x >> 5) + warp;
    const int nwarps = gridDim.x * (blockDim.x >> 5);

    for (int p = gwarp; p < n; p += nwarps) {
        const float x = f[p * C + lane];
        float total = 0.f;

        #pragma unroll
        for (int a = 0; a < 3; a++) {
            const float* __restrict__ Wa = &Wsm[a * 3072];
            float acc0 = Bsm[a][lane];
            float acc1 = 0.f;

            // center tap (always active)
            #pragma unroll
            for (int i = 0; i < 32; i += 2) {
                acc0 = fmaf(__shfl_sync(0xffffffffu, x, i),     Wa[1024 + i * 32 + lane],      acc0);
                acc1 = fmaf(__shfl_sync(0xffffffffu, x, i + 1), Wa[1024 + (i + 1) * 32 + lane], acc1);
            }

            const int ip = __ldg(&nbr_prev[a * n + p]);   // warp-uniform
            if (ip >= 0) {
                const float xp = __ldg(&f[ip * C + lane]);
                #pragma unroll
                for (int i = 0; i < 32; i += 2) {
                    acc0 = fmaf(__shfl_sync(0xffffffffu, xp, i),     Wa[i * 32 + lane],           acc0);
                    acc1 = fmaf(__shfl_sync(0xffffffffu, xp, i + 1), Wa[(i + 1) * 32 + lane],     acc1);
                }
            }

            const int nx = __ldg(&nbr_next[a * n + p]);   // warp-uniform
            if (nx >= 0) {
                const float xn = __ldg(&f[nx * C + lane]);
                #pragma unroll
                for (int i = 0; i < 32; i += 2) {
                    acc0 = fmaf(__shfl_sync(0xffffffffu, xn, i),     Wa[2048 + i * 32 + lane],       acc0);
                    acc1 = fmaf(__shfl_sync(0xffffffffu, xn, i + 1), Wa[2048 + (i + 1) * 32 + lane], acc1);
                }
            }

            const float acc = acc0 + acc1;
            total += 1.f / (1.f + __expf(-acc));   // sigmoid
        }

        out[p * C + lane] = total * x;
    }
}

extern "C" void kernel_launch(void* const* d_in, const int* in_sizes, int n_in,
                              void* d_out, int out_size) {
    const float* f     = (const float*)d_in[0];
    const int*   nprev = (const int*)  d_in[1];
    const int*   nnext = (const int*)  d_in[2];
    const float* W     = (const float*)d_in[3];
    const float* gamma = (const float*)d_in[4];
    const float* beta  = (const float*)d_in[5];
    const float* mean  = (const float*)d_in[6];
    const float* var   = (const float*)d_in[7];
    const int n = in_sizes[0] / C;

    recon_kernel<<<888, 256>>>(f, nprev, nnext, W, gamma, beta, mean, var,
                               (float*)d_out, n);
}

// round 2
// speedup vs baseline: 1.2429x; 1.2429x over previous
#include <cuda_runtime.h>
#include <cstdint>

#define C 32
#define EPS_BN 1e-5f
#define TPB 192

// ---------- f32x2 packed helpers (sm_103a) ----------
__device__ __forceinline__ unsigned long long pack2(float lo, float hi) {
    unsigned long long r;
    asm("mov.b64 %0, {%1, %2};" : "=l"(r) : "f"(lo), "f"(hi));
    return r;
}
__device__ __forceinline__ void unpack2(unsigned long long v, float& lo, float& hi) {
    asm("mov.b64 {%0, %1}, %2;" : "=f"(lo), "=f"(hi) : "l"(v));
}
__device__ __forceinline__ unsigned long long ffma2(unsigned long long a,
                                                    unsigned long long b,
                                                    unsigned long long c) {
    unsigned long long d;
    asm("fma.rn.f32x2 %0, %1, %2, %3;" : "=l"(d) : "l"(a), "l"(b), "l"(c));
    return d;
}

// Weights in smem, BN scale folded: Wq[t9][i][q] = float4 of W'[a,t,i,4q..4q+3]
// t9 = a*3 + t.  4KB per tap, 36KB total.
__device__ __forceinline__ void tap_accum(const float* __restrict__ buf,
                                          const float4* __restrict__ Wrow,
                                          unsigned long long acc[16]) {
#pragma unroll
    for (int i = 0; i < 32; i++) {
        const unsigned long long xp = pack2(buf[i], buf[i]);
        const ulonglong2* wr = (const ulonglong2*)(Wrow + i * 8);
#pragma unroll
        for (int q = 0; q < 8; q++) {
            ulonglong2 w = wr[q];                     // LDS.128 broadcast
            acc[2 * q]     = ffma2(xp, w.x, acc[2 * q]);
            acc[2 * q + 1] = ffma2(xp, w.y, acc[2 * q + 1]);
        }
    }
}

__device__ __forceinline__ void gather32(const float4* __restrict__ f4, int idx,
                                         float* __restrict__ buf) {
#pragma unroll
    for (int q = 0; q < 8; q++) {
        float4 v = (idx >= 0) ? __ldg(&f4[(long)idx * 8 + q])
                              : make_float4(0.f, 0.f, 0.f, 0.f);
        buf[4 * q + 0] = v.x; buf[4 * q + 1] = v.y;
        buf[4 * q + 2] = v.z; buf[4 * q + 3] = v.w;
    }
}

__device__ __forceinline__ float sigmoidf_(float v) {
    return 1.f / (1.f + __expf(-v));
}

__global__ __launch_bounds__(TPB, 2) void recon_kernel(
    const float* __restrict__ f,
    const int*   __restrict__ nbr_prev,
    const int*   __restrict__ nbr_next,
    const float* __restrict__ W,
    const float* __restrict__ gamma,
    const float* __restrict__ beta,
    const float* __restrict__ mean,
    const float* __restrict__ var,
    float* __restrict__ out, int n)
{
    __shared__ float4 Wq[9][32][8];               // 36KB folded weights
    __shared__ unsigned long long Bp[3][16];      // folded bias pairs

    const int tid = threadIdx.x;

    // Fold BN scale into weights: W'[a,t,i,j] = W * gamma[a,j]*rsqrt(var[a,j]+eps)
    for (int idx = tid; idx < 9 * 32 * 8; idx += TPB) {
        const int q  = idx & 7;
        const int i  = (idx >> 3) & 31;
        const int t9 = idx >> 8;          // 0..8
        const int a  = t9 / 3;
        const int j  = q * 4;
        float4 w = *(const float4*)&W[t9 * 1024 + i * 32 + j];
        w.x *= gamma[a * 32 + j + 0] * rsqrtf(var[a * 32 + j + 0] + EPS_BN);
        w.y *= gamma[a * 32 + j + 1] * rsqrtf(var[a * 32 + j + 1] + EPS_BN);
        w.z *= gamma[a * 32 + j + 2] * rsqrtf(var[a * 32 + j + 2] + EPS_BN);
        w.w *= gamma[a * 32 + j + 3] * rsqrtf(var[a * 32 + j + 3] + EPS_BN);
        Wq[t9][i][q] = w;
    }
    if (tid < 48) {
        const int a = tid / 16, j2 = tid & 15, j = 2 * j2;
        float s0 = gamma[a * 32 + j]     * rsqrtf(var[a * 32 + j]     + EPS_BN);
        float s1 = gamma[a * 32 + j + 1] * rsqrtf(var[a * 32 + j + 1] + EPS_BN);
        Bp[a][j2] = pack2(beta[a * 32 + j]     - mean[a * 32 + j]     * s0,
                          beta[a * 32 + j + 1] - mean[a * 32 + j + 1] * s1);
    }
    __syncthreads();

    const float4* __restrict__ f4 = (const float4*)f;
    const int T = gridDim.x * TPB;

    for (int base = blockIdx.x * TPB; base < n; base += T) {
        const int p = base + tid;
        const bool valid = (p < n);
        const int pp = valid ? p : (n - 1);

        // center feature vector, kept live for all branches + final gating
        float xr[32];
        gather32(f4, pp, xr);

        float tot[32];
#pragma unroll
        for (int j = 0; j < 32; j++) tot[j] = 0.f;

        float buf[32];

#pragma unroll
        for (int a = 0; a < 3; a++) {
            unsigned long long acc[16];
#pragma unroll
            for (int j2 = 0; j2 < 16; j2++) acc[j2] = Bp[a][j2];

            const int ip = nbr_prev[a * n + pp];
            if (__any_sync(0xffffffffu, ip >= 0)) {
                gather32(f4, ip, buf);
                tap_accum(buf, &Wq[a * 3 + 0][0][0], acc);
            }

            tap_accum(xr, &Wq[a * 3 + 1][0][0], acc);

            const int nx = nbr_next[a * n + pp];
            if (__any_sync(0xffffffffu, nx >= 0)) {
                gather32(f4, nx, buf);
                tap_accum(buf, &Wq[a * 3 + 2][0][0], acc);
            }

#pragma unroll
            for (int j2 = 0; j2 < 16; j2++) {
                float lo, hi;
                unpack2(acc[j2], lo, hi);
                tot[2 * j2]     += sigmoidf_(lo);
                tot[2 * j2 + 1] += sigmoidf_(hi);
            }
        }

        if (valid) {
            float4* o4 = (float4*)out;
#pragma unroll
            for (int q = 0; q < 8; q++) {
                float4 v;
                v.x = tot[4 * q + 0] * xr[4 * q + 0];
                v.y = tot[4 * q + 1] * xr[4 * q + 1];
                v.z = tot[4 * q + 2] * xr[4 * q + 2];
                v.w = tot[4 * q + 3] * xr[4 * q + 3];
                o4[(long)p * 8 + q] = v;
            }
        }
    }
}

extern "C" void kernel_launch(void* const* d_in, const int* in_sizes, int n_in,
                              void* d_out, int out_size) {
    const float* f     = (const float*)d_in[0];
    const int*   nprev = (const int*)  d_in[1];
    const int*   nnext = (const int*)  d_in[2];
    const float* W     = (const float*)d_in[3];
    const float* gamma = (const float*)d_in[4];
    const float* beta  = (const float*)d_in[5];
    const float* mean  = (const float*)d_in[6];
    const float* var   = (const float*)d_in[7];
    const int n = in_sizes[0] / C;

    recon_kernel<<<296, TPB>>>(f, nprev, nnext, W, gamma, beta, mean, var,
                               (float*)d_out, n);
}

// round 5
// speedup vs baseline: 2.9559x; 2.3782x over previous
#include <cuda_runtime.h>
#include <cuda_bf16.h>
#include <cstdint>

#define TPB 256
#define TILE 128
#define EPS_BN 1e-5f

// smem layout (bytes); all tile bases 1024-aligned for SWZ
#define OFF_BIAS 0          // 96 floats
#define OFF_IDX  384        // 7*128 ints
#define OFF_W    4096       // 9 taps * 4096B (32 rows x [64B hi | 64B lo])
#define OFF_C    40960      // center A tile: 128 rows x [64B hi | 64B lo]
#define OFF_P    57344      // prev-neighbor A tile
#define OFF_N    73728      // next-neighbor A tile
#define SMEM_TOTAL 90112

#define SWZ(o) ((o) ^ (((o) >> 3) & 0x70))

static __device__ __forceinline__ uint32_t smem_u32(const void* p) {
    uint32_t a;
    asm("{ .reg .u64 t; cvta.to.shared.u64 t, %1; cvt.u32.u64 %0, t; }" : "=r"(a) : "l"(p));
    return a;
}
// pack (lo_elem, hi_elem) -> bf16x2 (lo_elem in bits 0-15)
static __device__ __forceinline__ uint32_t pack_bf(float lo_elem, float hi_elem) {
    uint32_t r;
    asm("cvt.rn.bf16x2.f32 %0, %1, %2;" : "=r"(r) : "f"(hi_elem), "f"(lo_elem));
    return r;
}
static __device__ __forceinline__ void ldsm4(uint32_t* r, uint32_t addr) {
    asm volatile("ldmatrix.sync.aligned.m8n8.x4.shared.b16 {%0,%1,%2,%3}, [%4];"
                 : "=r"(r[0]), "=r"(r[1]), "=r"(r[2]), "=r"(r[3]) : "r"(addr));
}
static __device__ __forceinline__ void mma_bf16(float* d, const uint32_t* a,
                                                uint32_t b0, uint32_t b1) {
    asm volatile("mma.sync.aligned.m16n8k16.row.col.f32.bf16.bf16.f32 "
                 "{%0,%1,%2,%3}, {%4,%5,%6,%7}, {%8,%9}, {%0,%1,%2,%3};"
                 : "+f"(d[0]), "+f"(d[1]), "+f"(d[2]), "+f"(d[3])
                 : "r"(a[0]), "r"(a[1]), "r"(a[2]), "r"(a[3]), "r"(b0), "r"(b1));
}
static __device__ __forceinline__ float sigmoid_fast(float v) {
    float th;
    asm("tanh.approx.f32 %0, %1;" : "=f"(th) : "f"(0.5f * v));
    return fmaf(th, 0.5f, 0.5f);
}

// gather 128 rows of one group, fp32 -> bf16 hi/lo, swizzled store
static __device__ __forceinline__ void stage_group(char* smem, uint32_t dstoff,
                                                   const int* __restrict__ idxg,
                                                   const float4* __restrict__ f4,
                                                   int tid) {
    for (int s = tid; s < 1024; s += TPB) {
        const int r = s >> 3, q = s & 7;
        const int idx = idxg[r];
        float4 v = make_float4(0.f, 0.f, 0.f, 0.f);
        if (idx >= 0) v = __ldg(&f4[(long)idx * 8 + q]);
        const uint32_t h0 = pack_bf(v.x, v.y);
        const uint32_t h1 = pack_bf(v.z, v.w);
        const float f0 = __uint_as_float(h0 << 16);
        const float f1 = __uint_as_float(h0 & 0xFFFF0000u);
        const float f2 = __uint_as_float(h1 << 16);
        const float f3 = __uint_as_float(h1 & 0xFFFF0000u);
        const uint32_t l0 = pack_bf(v.x - f0, v.y - f1);
        const uint32_t l1 = pack_bf(v.z - f2, v.w - f3);
        char* d = smem + dstoff;
        *(uint2*)(d + SWZ(r * 128 + q * 8))      = make_uint2(h0, h1);
        *(uint2*)(d + SWZ(r * 128 + 64 + q * 8)) = make_uint2(l0, l1);
    }
}

__global__ __launch_bounds__(TPB, 2) void recon_kernel(
    const float* __restrict__ f,
    const int*   __restrict__ nbr_prev,
    const int*   __restrict__ nbr_next,
    const float* __restrict__ W,
    const float* __restrict__ gamma,
    const float* __restrict__ beta,
    const float* __restrict__ mean,
    const float* __restrict__ var,
    float* __restrict__ out, int n)
{
    extern __shared__ char smem[];
    const uint32_t sb = smem_u32(smem);
    const int tid  = threadIdx.x;
    const int lane = tid & 31;
    const int wid  = tid >> 5;

    float* biasm = (float*)(smem + OFF_BIAS);
    int*   idxb  = (int*)(smem + OFF_IDX);

    // ---- fold BN into weights, split bf16 hi/lo, store as [cout row][cin col] swizzled ----
    for (int s = tid; s < 9216; s += TPB) {
        const int t9 = s >> 10;
        const int i  = (s >> 5) & 31;       // cin
        const int j  = s & 31;              // cout
        const int a  = (t9 >= 6) ? 2 : (t9 >= 3 ? 1 : 0);
        const float sc = gamma[a * 32 + j] * rsqrtf(var[a * 32 + j] + EPS_BN);
        const float w  = W[s] * sc;
        const __nv_bfloat16 hb = __float2bfloat16(w);
        const float hf = __bfloat162float(hb);
        const __nv_bfloat16 lb = __float2bfloat16(w - hf);
        char* bt = smem + OFF_W + t9 * 4096;
        *(__nv_bfloat16*)(bt + SWZ(j * 128 + 2 * i))      = hb;
        *(__nv_bfloat16*)(bt + SWZ(j * 128 + 64 + 2 * i)) = lb;
    }
    if (tid < 96) {
        const int a = tid >> 5;
        const float sc = gamma[tid] * rsqrtf(var[tid] + EPS_BN);
        biasm[tid] = beta[tid] - mean[tid] * sc;
    }
    __syncthreads();

    const float4* __restrict__ f4 = (const float4*)f;
    const int ntiles = (n + TILE - 1) / TILE;

    // per-lane ldmatrix geometry
    const int lr  = lane & 7;
    const int mid = lane >> 3;
    // A frags: m0:(r0-7,klo) m1:(r8-15,klo) m2:(r0-7,khi) m3:(r8-15,khi)
    const int arow   = wid * 16 + ((mid & 1) << 3) + lr;
    const int akunit = (mid >> 1) << 4;                  // 16B unit within k16
    // B frags: m0:bHi u0, m1:bHi u1, m2:bLo u0, m3:bLo u1
    const int bvar   = (mid & 2) << 5;                   // +64 for lo
    const int bkunit = (mid & 1) << 4;

    for (int tile = blockIdx.x; tile < ntiles; tile += gridDim.x) {
        const int pbase = tile * TILE;

        // stage gather indices: g=0 center, 1+2a prev_a, 2+2a next_a
        for (int s = tid; s < 896; s += TPB) {
            const int g = s >> 7, r = s & 127;
            const int p = pbase + r;
            int idx = -1;
            if (p < n) {
                if (g == 0) idx = p;
                else {
                    const int a = (g - 1) >> 1;
                    idx = ((g - 1) & 1) ? nbr_next[a * n + p] : nbr_prev[a * n + p];
                }
            }
            idxb[s] = idx;
        }
        __syncthreads();

        stage_group(smem, OFF_C, idxb,       f4, tid);
        stage_group(smem, OFF_P, idxb + 128, f4, tid);   // prev a=0
        stage_group(smem, OFF_N, idxb + 256, f4, tid);   // next a=0
        __syncthreads();

        float tot[4][4];
        #pragma unroll
        for (int nc = 0; nc < 4; nc++)
            #pragma unroll
            for (int k = 0; k < 4; k++) tot[nc][k] = 0.f;

        #pragma unroll
        for (int a = 0; a < 3; a++) {
            float acc[4][4];
            #pragma unroll
            for (int nc = 0; nc < 4; nc++) {
                const int n0 = 8 * nc + 2 * (lane & 3);
                const float2 b2 = *(const float2*)&biasm[a * 32 + n0];
                acc[nc][0] = acc[nc][2] = b2.x;
                acc[nc][1] = acc[nc][3] = b2.y;
            }
            #pragma unroll
            for (int t = 0; t < 3; t++) {
                const uint32_t gb = sb + (t == 0 ? OFF_P : (t == 1 ? OFF_C : OFF_N));
                const uint32_t wb = sb + OFF_W + (a * 3 + t) * 4096;
                uint32_t ah[2][4], al[2][4];
                #pragma unroll
                for (int ks = 0; ks < 2; ks++) {
                    ldsm4(ah[ks], gb + SWZ(arow * 128 + ks * 32 + akunit));
                    ldsm4(al[ks], gb + SWZ(arow * 128 + 64 + ks * 32 + akunit));
                }
                #pragma unroll
                for (int ks = 0; ks < 2; ks++) {
                    #pragma unroll
                    for (int nc = 0; nc < 4; nc++) {
                        uint32_t b[4];
                        ldsm4(b, wb + SWZ((8 * nc + lr) * 128 + bvar + ks * 32 + bkunit));
                        mma_bf16(acc[nc], ah[ks], b[0], b[1]);   // hi * Whi
                        mma_bf16(acc[nc], al[ks], b[0], b[1]);   // lo * Whi
                        mma_bf16(acc[nc], ah[ks], b[2], b[3]);   // hi * Wlo
                    }
                }
            }
            #pragma unroll
            for (int nc = 0; nc < 4; nc++)
                #pragma unroll
                for (int k = 0; k < 4; k++) tot[nc][k] += sigmoid_fast(acc[nc][k]);

            __syncthreads();                 // all warps done reading P/N
            if (a < 2) {
                stage_group(smem, OFF_P, idxb + 128 * (3 + 2 * a), f4, tid);
                stage_group(smem, OFF_N, idxb + 128 * (4 + 2 * a), f4, tid);
                __syncthreads();
            }
        }

        // ---- epilogue: gate by x (reconstructed hi+lo from center tile) + store ----
        const int prow0 = pbase + wid * 16 + (lane >> 2);
        #pragma unroll
        for (int np = 0; np < 2; np++) {
            const int xrow = wid * 16 + ((mid & 1) << 3) + lr;
            const int xnc  = 2 * np + (mid >> 1);
            uint32_t xh[4], xl[4];
            ldsm4(xh, sb + OFF_C + SWZ(xrow * 128 + xnc * 16));
            ldsm4(xl, sb + OFF_C + SWZ(xrow * 128 + 64 + xnc * 16));
            #pragma unroll
            for (int h = 0; h < 2; h++) {
                const int nc = 2 * np + h;
                #pragma unroll
                for (int rr = 0; rr < 2; rr++) {
                    const uint32_t rh = xh[2 * h + rr], rl = xl[2 * h + rr];
                    const float x0 = __uint_as_float(rh << 16) + __uint_as_float(rl << 16);
                    const float x1 = __uint_as_float(rh & 0xFFFF0000u) +
                                     __uint_as_float(rl & 0xFFFF0000u);
                    const int p = prow0 + 8 * rr;
                    if (p < n) {
                        float2 v;
                        v.x = tot[nc][2 * rr]     * x0;
                        v.y = tot[nc][2 * rr + 1] * x1;
                        *(float2*)&out[(long)p * 32 + 8 * nc + 2 * (lane & 3)] = v;
                    }
                }
            }
        }
        __syncthreads();   // protect OFF_C / idx before next tile's staging
    }
}

extern "C" void kernel_launch(void* const* d_in, const int* in_sizes, int n_in,
                              void* d_out, int out_size) {
    const float* f     = (const float*)d_in[0];
    const int*   nprev = (const int*)  d_in[1];
    const int*   nnext = (const int*)  d_in[2];
    const float* W     = (const float*)d_in[3];
    const float* gamma = (const float*)d_in[4];
    const float* beta  = (const float*)d_in[5];
    const float* mean  = (const float*)d_in[6];
    const float* var   = (const float*)d_in[7];
    const int n = in_sizes[0] / 32;

    cudaFuncSetAttribute(recon_kernel, cudaFuncAttributeMaxDynamicSharedMemorySize,
                         SMEM_TOTAL);
    recon_kernel<<<296, TPB, SMEM_TOTAL>>>(f, nprev, nnext, W, gamma, beta, mean, var,
                                           (float*)d_out, n);
}

// round 6
// speedup vs baseline: 3.9483x; 1.3358x over previous
#include <cuda_runtime.h>
#include <cuda_bf16.h>
#include <cstdint>

#define TPB 384
#define TILE 192
#define EPS_BN 1e-5f

// smem layout (bytes); tile bases 1024-aligned
#define OFF_BIAS 0                    // 96 floats
#define OFF_W    1024                 // 9 taps * 4096B
#define OFF_C    37888                // center tile: 192 rows x 128B
#define OFF_G    62464                // 6 neighbor tiles * 24576B
#define SMEM_TOTAL 209920

#define SWZ(o) ((o) ^ (((o) >> 3) & 0x70))

// feature scratch: row p = 128B [hi 64B | lo 64B], bf16
__device__ uint4 g_fhl[8 * 1000448];

static __device__ __forceinline__ uint32_t smem_u32(const void* p) {
    uint32_t a;
    asm("{ .reg .u64 t; cvta.to.shared.u64 t, %1; cvt.u32.u64 %0, t; }" : "=r"(a) : "l"(p));
    return a;
}
static __device__ __forceinline__ uint32_t pack_bf(float lo_elem, float hi_elem) {
    uint32_t r;
    asm("cvt.rn.bf16x2.f32 %0, %1, %2;" : "=r"(r) : "f"(hi_elem), "f"(lo_elem));
    return r;
}
static __device__ __forceinline__ void ldsm4(uint32_t* r, uint32_t addr) {
    asm volatile("ldmatrix.sync.aligned.m8n8.x4.shared.b16 {%0,%1,%2,%3}, [%4];"
                 : "=r"(r[0]), "=r"(r[1]), "=r"(r[2]), "=r"(r[3]) : "r"(addr));
}
static __device__ __forceinline__ void mma_bf16(float* d, const uint32_t* a,
                                                uint32_t b0, uint32_t b1) {
    asm volatile("mma.sync.aligned.m16n8k16.row.col.f32.bf16.bf16.f32 "
                 "{%0,%1,%2,%3}, {%4,%5,%6,%7}, {%8,%9}, {%0,%1,%2,%3};"
                 : "+f"(d[0]), "+f"(d[1]), "+f"(d[2]), "+f"(d[3])
                 : "r"(a[0]), "r"(a[1]), "r"(a[2]), "r"(a[3]), "r"(b0), "r"(b1));
}
static __device__ __forceinline__ void cp16(uint32_t dst, const void* src, uint32_t bytes) {
    const size_t gsrc = __cvta_generic_to_global(src);
    asm volatile("cp.async.cg.shared.global [%0], [%1], 16, %2;"
                 :: "r"(dst), "l"(gsrc), "r"(bytes) : "memory");
}
static __device__ __forceinline__ float sigmoid_fast(float v) {
    float th;
    asm("tanh.approx.f32 %0, %1;" : "=f"(th) : "f"(0.5f * v));
    return fmaf(th, 0.5f, 0.5f);
}

// ---- prepass: fp32 features -> [hi|lo] bf16 rows ----
__global__ __launch_bounds__(256) void convert_kernel(const float4* __restrict__ f4,
                                                      int n) {
    const int p = blockIdx.x * 256 + threadIdx.x;
    if (p >= n) return;
    uint32_t h[16], l[16];
#pragma unroll
    for (int q = 0; q < 8; q++) {
        const float4 v = __ldg(&f4[(long)p * 8 + q]);
        const uint32_t h0 = pack_bf(v.x, v.y);
        const uint32_t h1 = pack_bf(v.z, v.w);
        const float f0 = __uint_as_float(h0 << 16);
        const float f1 = __uint_as_float(h0 & 0xFFFF0000u);
        const float f2 = __uint_as_float(h1 << 16);
        const float f3 = __uint_as_float(h1 & 0xFFFF0000u);
        h[2 * q] = h0; h[2 * q + 1] = h1;
        l[2 * q]     = pack_bf(v.x - f0, v.y - f1);
        l[2 * q + 1] = pack_bf(v.z - f2, v.w - f3);
    }
#pragma unroll
    for (int j = 0; j < 4; j++) {
        g_fhl[(long)p * 8 + j]     = make_uint4(h[4 * j], h[4 * j + 1], h[4 * j + 2], h[4 * j + 3]);
        g_fhl[(long)p * 8 + 4 + j] = make_uint4(l[4 * j], l[4 * j + 1], l[4 * j + 2], l[4 * j + 3]);
    }
}

__global__ __launch_bounds__(TPB, 1) void recon_kernel(
    const int*   __restrict__ nbr_prev,
    const int*   __restrict__ nbr_next,
    const float* __restrict__ W,
    const float* __restrict__ gamma,
    const float* __restrict__ beta,
    const float* __restrict__ mean,
    const float* __restrict__ var,
    float* __restrict__ out, int n)
{
    extern __shared__ char smem[];
    const uint32_t sb = smem_u32(smem);
    const int tid  = threadIdx.x;
    const int lane = tid & 31;
    const int wid  = tid >> 5;

    float* biasm = (float*)(smem + OFF_BIAS);

    // ---- fold BN into weights, split bf16 hi/lo, swizzled B tiles ----
    for (int s = tid; s < 9216; s += TPB) {
        const int t9 = s >> 10;
        const int i  = (s >> 5) & 31;       // cin
        const int j  = s & 31;              // cout
        const int a  = (t9 >= 6) ? 2 : (t9 >= 3 ? 1 : 0);
        const float sc = gamma[a * 32 + j] * rsqrtf(var[a * 32 + j] + EPS_BN);
        const float w  = W[s] * sc;
        const __nv_bfloat16 hb = __float2bfloat16(w);
        const float hf = __bfloat162float(hb);
        const __nv_bfloat16 lb = __float2bfloat16(w - hf);
        char* bt = smem + OFF_W + t9 * 4096;
        *(__nv_bfloat16*)(bt + SWZ(j * 128 + 2 * i))      = hb;
        *(__nv_bfloat16*)(bt + SWZ(j * 128 + 64 + 2 * i)) = lb;
    }
    if (tid < 96) {
        const float sc = gamma[tid] * rsqrtf(var[tid] + EPS_BN);
        biasm[tid] = beta[tid] - mean[tid] * sc;
    }
    __syncthreads();

    const int ntiles = (n + TILE - 1) / TILE;

    // per-lane ldmatrix geometry (verified in R5)
    const int lr  = lane & 7;
    const int mid = lane >> 3;
    const int arow   = wid * 16 + ((mid & 1) << 3) + lr;
    const int akunit = (mid >> 1) << 4;
    const int bvar   = (mid & 2) << 5;
    const int bkunit = (mid & 1) << 4;

    for (int tile = blockIdx.x; tile < ntiles; tile += gridDim.x) {
        const int pbase = tile * TILE;

        // ---- single async staging phase: neighbor idx loads first ----
        int idxv[3];
#pragma unroll
        for (int k = 0; k < 3; k++) {
            const int s = tid + k * TPB;        // 0..1151
            const int g = s / TILE;
            const int r = s - g * TILE;
            const int p = pbase + r;
            const int a = g >> 1;
            idxv[k] = (p < n) ? ((g & 1) ? __ldg(&nbr_next[a * n + p])
                                         : __ldg(&nbr_prev[a * n + p])) : -1;
        }
        // center tile (no idx dependency) — hides idx LDG latency
#pragma unroll
        for (int k = 0; k < 4; k++) {
            const int s = tid + k * TPB;        // 0..1535
            const int r = s >> 3, u = s & 7;
            const int p = pbase + r;
            const int rowc = (p < n) ? p : 0;
            cp16(sb + OFF_C + SWZ(r * 128 + u * 16),
                 &g_fhl[(long)rowc * 8 + u], (p < n) ? 16u : 0u);
        }
        // neighbor tiles
#pragma unroll
        for (int k = 0; k < 3; k++) {
            const int s = tid + k * TPB;
            const int g = s / TILE;
            const int r = s - g * TILE;
            const int idx = idxv[k];
            const int rowc = (idx >= 0) ? idx : 0;
            const uint32_t dbase = sb + OFF_G + g * 24576;
#pragma unroll
            for (int u = 0; u < 8; u++)
                cp16(dbase + SWZ(r * 128 + u * 16),
                     &g_fhl[(long)rowc * 8 + u], (idx >= 0) ? 16u : 0u);
        }
        asm volatile("cp.async.commit_group;" ::: "memory");
        asm volatile("cp.async.wait_group 0;" ::: "memory");
        __syncthreads();

        // ---- all 3 branches back-to-back ----
        float tot[4][4];
#pragma unroll
        for (int nc = 0; nc < 4; nc++)
#pragma unroll
            for (int k = 0; k < 4; k++) tot[nc][k] = 0.f;

#pragma unroll
        for (int a = 0; a < 3; a++) {
            float acc[4][4];
#pragma unroll
            for (int nc = 0; nc < 4; nc++) {
                const int n0 = 8 * nc + 2 * (lane & 3);
                const float2 b2 = *(const float2*)&biasm[a * 32 + n0];
                acc[nc][0] = acc[nc][2] = b2.x;
                acc[nc][1] = acc[nc][3] = b2.y;
            }
#pragma unroll
            for (int t = 0; t < 3; t++) {
                const uint32_t gb = (t == 1) ? (sb + OFF_C)
                                             : (sb + OFF_G + (2 * a + (t == 2)) * 24576);
                const uint32_t wb = sb + OFF_W + (a * 3 + t) * 4096;
                uint32_t ah[2][4], al[2][4];
#pragma unroll
                for (int ks = 0; ks < 2; ks++) {
                    ldsm4(ah[ks], gb + SWZ(arow * 128 + ks * 32 + akunit));
                    ldsm4(al[ks], gb + SWZ(arow * 128 + 64 + ks * 32 + akunit));
                }
#pragma unroll
                for (int ks = 0; ks < 2; ks++) {
#pragma unroll
                    for (int nc = 0; nc < 4; nc++) {
                        uint32_t b[4];
                        ldsm4(b, wb + SWZ((8 * nc + lr) * 128 + bvar + ks * 32 + bkunit));
                        mma_bf16(acc[nc], ah[ks], b[0], b[1]);   // hi * Whi
                        mma_bf16(acc[nc], al[ks], b[0], b[1]);   // lo * Whi
                        mma_bf16(acc[nc], ah[ks], b[2], b[3]);   // hi * Wlo
                    }
                }
            }
#pragma unroll
            for (int nc = 0; nc < 4; nc++)
#pragma unroll
                for (int k = 0; k < 4; k++) tot[nc][k] += sigmoid_fast(acc[nc][k]);
        }

        // ---- epilogue: gate by x (hi+lo reconstruct from center tile) + store ----
        const int prow0 = pbase + wid * 16 + (lane >> 2);
#pragma unroll
        for (int np = 0; np < 2; np++) {
            const int xrow = wid * 16 + ((mid & 1) << 3) + lr;
            const int xnc  = 2 * np + (mid >> 1);
            uint32_t xh[4], xl[4];
            ldsm4(xh, sb + OFF_C + SWZ(xrow * 128 + xnc * 16));
            ldsm4(xl, sb + OFF_C + SWZ(xrow * 128 + 64 + xnc * 16));
#pragma unroll
            for (int h = 0; h < 2; h++) {
                const int nc = 2 * np + h;
#pragma unroll
                for (int rr = 0; rr < 2; rr++) {
                    const uint32_t rh = xh[2 * h + rr], rl = xl[2 * h + rr];
                    const float x0 = __uint_as_float(rh << 16) + __uint_as_float(rl << 16);
                    const float x1 = __uint_as_float(rh & 0xFFFF0000u) +
                                     __uint_as_float(rl & 0xFFFF0000u);
                    const int p = prow0 + 8 * rr;
                    if (p < n) {
                        float2 v;
                        v.x = tot[nc][2 * rr]     * x0;
                        v.y = tot[nc][2 * rr + 1] * x1;
                        *(float2*)&out[(long)p * 32 + 8 * nc + 2 * (lane & 3)] = v;
                    }
                }
            }
        }
        __syncthreads();   // protect smem tiles before next tile's staging
    }
}

extern "C" void kernel_launch(void* const* d_in, const int* in_sizes, int n_in,
                              void* d_out, int out_size) {
    const float* f     = (const float*)d_in[0];
    const int*   nprev = (const int*)  d_in[1];
    const int*   nnext = (const int*)  d_in[2];
    const float* W     = (const float*)d_in[3];
    const float* gamma = (const float*)d_in[4];
    const float* beta  = (const float*)d_in[5];
    const float* mean  = (const float*)d_in[6];
    const float* var   = (const float*)d_in[7];
    const int n = in_sizes[0] / 32;

    convert_kernel<<<(n + 255) / 256, 256>>>((const float4*)f, n);

    cudaFuncSetAttribute(recon_kernel, cudaFuncAttributeMaxDynamicSharedMemorySize,
                         SMEM_TOTAL);
    recon_kernel<<<148, TPB, SMEM_TOTAL>>>(nprev, nnext, W, gamma, beta, mean, var,
                                           (float*)d_out, n);
}

// round 7
// speedup vs baseline: 5.2314x; 1.3250x over previous
#include <cuda_runtime.h>
#include <cstdint>

#define TPB 384
#define TILE 64
#define EPS_BN 1e-5f
#define RSTRIDE 40

// smem byte offsets
#define OFF_BIAS 0                 // 96 floats
#define OFF_W    1024              // 9 taps * 4096B (32 k-rows x 128B, tf32-rounded fp32)
#define OFF_T0   37888             // 7 groups * 8192B (64 rows x 128B fp32, SWZ)
#define OFF_T1   95232
#define OFF_R    152576            // 3 * 64 * RSTRIDE * 4 = 30720
#define SMEM_TOTAL 184320

#define SWZ(o) ((o) ^ (((o) >> 3) & 0x70))

static __device__ __forceinline__ uint32_t smem_u32(const void* p) {
    uint32_t a;
    asm("{ .reg .u64 t; cvta.to.shared.u64 t, %1; cvt.u32.u64 %0, t; }" : "=r"(a) : "l"(p));
    return a;
}
static __device__ __forceinline__ uint32_t cvt_tf32(float x) {
    uint32_t r;
    asm("cvt.rna.tf32.f32 %0, %1;" : "=r"(r) : "f"(x));
    return r;
}
static __device__ __forceinline__ uint32_t lds32(uint32_t a) {
    uint32_t r;
    asm volatile("ld.shared.b32 %0, [%1];" : "=r"(r) : "r"(a));
    return r;
}
static __device__ __forceinline__ float4 lds128f(uint32_t a) {
    float4 v;
    asm volatile("ld.shared.v4.f32 {%0,%1,%2,%3}, [%4];"
                 : "=f"(v.x), "=f"(v.y), "=f"(v.z), "=f"(v.w) : "r"(a));
    return v;
}
static __device__ __forceinline__ void mma_tf32(float* d, uint32_t a0, uint32_t a1,
                                                uint32_t a2, uint32_t a3,
                                                uint32_t b0, uint32_t b1) {
    asm volatile("mma.sync.aligned.m16n8k8.row.col.f32.tf32.tf32.f32 "
                 "{%0,%1,%2,%3}, {%4,%5,%6,%7}, {%8,%9}, {%0,%1,%2,%3};"
                 : "+f"(d[0]), "+f"(d[1]), "+f"(d[2]), "+f"(d[3])
                 : "r"(a0), "r"(a1), "r"(a2), "r"(a3), "r"(b0), "r"(b1));
}
static __device__ __forceinline__ void cp16(uint32_t dst, const float4* src, uint32_t bytes) {
    const size_t g = __cvta_generic_to_global(src);
    asm volatile("cp.async.cg.shared.global [%0], [%1], 16, %2;"
                 :: "r"(dst), "l"(g), "r"(bytes) : "memory");
}
static __device__ __forceinline__ float sigmoid_fast(float v) {
    float th;
    asm("tanh.approx.f32 %0, %1;" : "=f"(th) : "f"(0.5f * v));
    return fmaf(th, 0.5f, 0.5f);
}

// stage one tile (center + this thread's neighbor row) into buffer tb
static __device__ __forceinline__ void stage_tile(uint32_t tb, int pbase, int n,
                                                  int myidx, int tid,
                                                  const float4* __restrict__ f4) {
    // center group (512 cp16 over 384 threads)
    #pragma unroll
    for (int k = 0; k < 2; k++) {
        const int s = tid + k * TPB;
        if (s < 512) {
            const int r = s >> 3, u = s & 7;
            const int p = pbase + r;
            const long rowc = (p < n) ? p : 0;
            cp16(tb + SWZ(r * 128 + u * 16), &f4[rowc * 8 + u], (p < n) ? 16u : 0u);
        }
    }
    // neighbor groups: thread owns (g = tid>>6, r = tid&63)
    const int g = tid >> 6, r = tid & 63;
    const uint32_t db = tb + (1 + g) * 8192;
    const long rowc = (myidx >= 0) ? myidx : 0;
    const uint32_t bytes = (myidx >= 0) ? 16u : 0u;
    #pragma unroll
    for (int u = 0; u < 8; u++)
        cp16(db + SWZ(r * 128 + u * 16), &f4[rowc * 8 + u], bytes);
}

__global__ __launch_bounds__(TPB, 1) void recon_kernel(
    const float* __restrict__ f,
    const int*   __restrict__ nbr_prev,
    const int*   __restrict__ nbr_next,
    const float* __restrict__ W,
    const float* __restrict__ gamma,
    const float* __restrict__ beta,
    const float* __restrict__ mean,
    const float* __restrict__ var,
    float* __restrict__ out, int n)
{
    extern __shared__ char smem[];
    const uint32_t sb = smem_u32(smem);
    const int tid  = threadIdx.x;
    const int lane = tid & 31;
    const int wid  = tid >> 5;
    const int rg   = wid & 3;        // row group (16 rows)
    const int br   = wid >> 2;       // branch 0..2

    float*    biasm = (float*)(smem + OFF_BIAS);
    uint32_t* Wsm   = (uint32_t*)(smem + OFF_W);
    float*    redf  = (float*)(smem + OFF_R);

    // ---- fold BN into weights, tf32-round, store [tap][k=cin row 128B][n=cout] ----
    for (int s = tid; s < 9216; s += TPB) {
        const int t9 = s >> 10;
        const int i  = (s >> 5) & 31;      // cin (k)
        const int j  = s & 31;             // cout (n)
        const int a  = (t9 >= 6) ? 2 : (t9 >= 3 ? 1 : 0);
        const float sc = gamma[a * 32 + j] * rsqrtf(var[a * 32 + j] + EPS_BN);
        Wsm[t9 * 1024 + i * 32 + j] = cvt_tf32(W[s] * sc);
    }
    if (tid < 96) {
        const float sc = gamma[tid] * rsqrtf(var[tid] + EPS_BN);
        biasm[tid] = beta[tid] - mean[tid] * sc;
    }
    __syncthreads();

    // ---- preload this branch's B fragments (once per kernel) ----
    uint32_t breg[3][4][4][2];
    #pragma unroll
    for (int t = 0; t < 3; t++) {
        const uint32_t wb = sb + OFF_W + (br * 3 + t) * 4096;
        #pragma unroll
        for (int ks = 0; ks < 4; ks++)
            #pragma unroll
            for (int nc = 0; nc < 4; nc++) {
                const uint32_t a0 = wb + (ks * 8 + (lane & 3)) * 128 +
                                    (8 * nc + (lane >> 2)) * 4;
                breg[t][ks][nc][0] = lds32(a0);
                breg[t][ks][nc][1] = lds32(a0 + 4 * 128);
            }
    }

    const float4* __restrict__ f4 = (const float4*)f;
    const int ntiles = (n + TILE - 1) / TILE;
    const int grid = gridDim.x;

    // ---- prologue: stage first tile into buf0 ----
    int tile = blockIdx.x;
    {
        const int g = tid >> 6, a = g >> 1, r = tid & 63;
        const int p = tile * TILE + r;
        int idx = -1;
        if (tile < ntiles && p < n)
            idx = (g & 1) ? __ldg(&nbr_next[a * n + p]) : __ldg(&nbr_prev[a * n + p]);
        if (tile < ntiles) stage_tile(sb + OFF_T0, tile * TILE, n, idx, tid, f4);
        asm volatile("cp.async.commit_group;" ::: "memory");
    }

    const int r0 = rg * 16 + (lane >> 2);     // A base row within tile
    const int kb0 = (lane & 3) * 4;           // A k-col byte offset

    int cur = 0;
    for (; tile < ntiles; tile += grid) {
        asm volatile("cp.async.wait_group 0;" ::: "memory");
        __syncthreads();
        const uint32_t tb = sb + (cur ? OFF_T1 : OFF_T0);
        const int pbase = tile * TILE;
        const int ntile = tile + grid;

        // issue next tile's neighbor-index load early (latency hidden by MMA)
        int nidx = -1;
        {
            const int g = tid >> 6, a = g >> 1, r = tid & 63;
            const int p = ntile * TILE + r;
            if (ntile < ntiles && p < n)
                nidx = (g & 1) ? __ldg(&nbr_next[a * n + p]) : __ldg(&nbr_prev[a * n + p]);
        }

        // ---- MMAs: this warp's branch only; B frags resident in regs ----
        float acc[4][4];
        #pragma unroll
        for (int nc = 0; nc < 4; nc++) {
            const float2 b2 = *(const float2*)&biasm[br * 32 + 8 * nc + 2 * (lane & 3)];
            acc[nc][0] = acc[nc][2] = b2.x;
            acc[nc][1] = acc[nc][3] = b2.y;
        }
        #pragma unroll
        for (int t = 0; t < 3; t++) {
            const uint32_t gb = tb + ((t == 1) ? 0 : ((t == 0) ? (1 + 2 * br)
                                                               : (2 + 2 * br))) * 8192;
            #pragma unroll
            for (int ks = 0; ks < 4; ks++) {
                const uint32_t o = (uint32_t)(r0 * 128 + ks * 32 + kb0);
                const uint32_t u0 = gb + SWZ(o);
                const uint32_t u1 = gb + SWZ(o + 16);
                const uint32_t a0 = cvt_tf32(__uint_as_float(lds32(u0)));
                const uint32_t a1 = cvt_tf32(__uint_as_float(lds32(u0 + 1024)));
                const uint32_t a2 = cvt_tf32(__uint_as_float(lds32(u1)));
                const uint32_t a3 = cvt_tf32(__uint_as_float(lds32(u1 + 1024)));
                #pragma unroll
                for (int nc = 0; nc < 4; nc++)
                    mma_tf32(acc[nc], a0, a1, a2, a3,
                             breg[t][ks][nc][0], breg[t][ks][nc][1]);
            }
        }

        // ---- stage next tile into other buffer (overlaps with rest) ----
        if (ntile < ntiles)
            stage_tile(sb + (cur ? OFF_T0 : OFF_T1), ntile * TILE, n, nidx, tid, f4);
        asm volatile("cp.async.commit_group;" ::: "memory");

        // ---- sigmoid + partial store (conflict-free stride-40) ----
        #pragma unroll
        for (int nc = 0; nc < 4; nc++)
            #pragma unroll
            for (int rr = 0; rr < 2; rr++) {
                const int rowp = rg * 16 + (lane >> 2) + 8 * rr;
                const uint32_t addr = sb + OFF_R +
                    (((br * 64 + rowp) * RSTRIDE + 8 * nc + 2 * (lane & 3)) << 2);
                asm volatile("st.shared.v2.f32 [%0], {%1, %2};"
                             :: "r"(addr), "f"(sigmoid_fast(acc[nc][2 * rr])),
                                "f"(sigmoid_fast(acc[nc][2 * rr + 1])) : "memory");
            }
        __syncthreads();

        // ---- epilogue: sum 3 branches, gate by exact fp32 x, store ----
        #pragma unroll
        for (int k = 0; k < 2; k++) {
            const int s = tid + k * TPB;
            if (s < 512) {
                const int row = s >> 3, q = s & 7;
                const uint32_t rb = sb + OFF_R + ((row * RSTRIDE + 4 * q) << 2);
                const float4 s0 = lds128f(rb);
                const float4 s1 = lds128f(rb + 64 * RSTRIDE * 4);
                const float4 s2 = lds128f(rb + 128 * RSTRIDE * 4);
                const float4 x  = lds128f(tb + SWZ(row * 128 + q * 16));
                const int p = pbase + row;
                if (p < n) {
                    float4 v;
                    v.x = (s0.x + s1.x + s2.x) * x.x;
                    v.y = (s0.y + s1.y + s2.y) * x.y;
                    v.z = (s0.z + s1.z + s2.z) * x.z;
                    v.w = (s0.w + s1.w + s2.w) * x.w;
                    ((float4*)out)[(long)p * 8 + q] = v;
                }
            }
        }
        __syncthreads();
        cur ^= 1;
    }
}

extern "C" void kernel_launch(void* const* d_in, const int* in_sizes, int n_in,
                              void* d_out, int out_size) {
    const float* f     = (const float*)d_in[0];
    const int*   nprev = (const int*)  d_in[1];
    const int*   nnext = (const int*)  d_in[2];
    const float* W     = (const float*)d_in[3];
    const float* gamma = (const float*)d_in[4];
    const float* beta  = (const float*)d_in[5];
    const float* mean  = (const float*)d_in[6];
    const float* var   = (const float*)d_in[7];
    const int n = in_sizes[0] / 32;

    cudaFuncSetAttribute(recon_kernel, cudaFuncAttributeMaxDynamicSharedMemorySize,
                         SMEM_TOTAL);
    recon_kernel<<<148, TPB, SMEM_TOTAL>>>(f, nprev, nnext, W, gamma, beta, mean, var,
                                           (float*)d_out, n);
}

// round 8
// speedup vs baseline: 5.6041x; 1.0712x over previous
#include <cuda_runtime.h>
#include <cstdint>

#define TPB 384
#define TILE 64
#define EPS_BN 1e-5f
#define RSTRIDE 40

// smem byte offsets
#define OFF_BIAS 0                 // 96 floats
#define OFF_W    1024              // 9 taps * 4096B (32 k-rows x 128B, tf32-rounded fp32)
#define OFF_T0   37888             // 7 groups * 8192B (64 rows x 128B fp32, SWZ)
#define OFF_T1   95232
#define OFF_R    152576            // 3 * 64 * RSTRIDE * 4 = 30720
#define SMEM_TOTAL 184320

#define SWZ(o) ((o) ^ (((o) >> 3) & 0x70))

static __device__ __forceinline__ uint32_t smem_u32(const void* p) {
    uint32_t a;
    asm("{ .reg .u64 t; cvta.to.shared.u64 t, %1; cvt.u32.u64 %0, t; }" : "=r"(a) : "l"(p));
    return a;
}
static __device__ __forceinline__ uint32_t cvt_tf32(float x) {
    uint32_t r;
    asm("cvt.rna.tf32.f32 %0, %1;" : "=r"(r) : "f"(x));
    return r;
}
static __device__ __forceinline__ uint32_t lds32(uint32_t a) {
    uint32_t r;
    asm volatile("ld.shared.b32 %0, [%1];" : "=r"(r) : "r"(a));
    return r;
}
static __device__ __forceinline__ float4 lds128f(uint32_t a) {
    float4 v;
    asm volatile("ld.shared.v4.f32 {%0,%1,%2,%3}, [%4];"
                 : "=f"(v.x), "=f"(v.y), "=f"(v.z), "=f"(v.w) : "r"(a));
    return v;
}
static __device__ __forceinline__ void mma_tf32(float* d, uint32_t a0, uint32_t a1,
                                                uint32_t a2, uint32_t a3,
                                                uint32_t b0, uint32_t b1) {
    asm volatile("mma.sync.aligned.m16n8k8.row.col.f32.tf32.tf32.f32 "
                 "{%0,%1,%2,%3}, {%4,%5,%6,%7}, {%8,%9}, {%0,%1,%2,%3};"
                 : "+f"(d[0]), "+f"(d[1]), "+f"(d[2]), "+f"(d[3])
                 : "r"(a0), "r"(a1), "r"(a2), "r"(a3), "r"(b0), "r"(b1));
}
static __device__ __forceinline__ void cp16(uint32_t dst, const float4* src, uint32_t bytes) {
    const size_t g = __cvta_generic_to_global(src);
    asm volatile("cp.async.cg.shared.global [%0], [%1], 16, %2;"
                 :: "r"(dst), "l"(g), "r"(bytes) : "memory");
}
static __device__ __forceinline__ float sigmoid_fast(float v) {
    float th;
    asm("tanh.approx.f32 %0, %1;" : "=f"(th) : "f"(0.5f * v));
    return fmaf(th, 0.5f, 0.5f);
}

// stage one tile (center + this thread's neighbor row) into buffer tb
static __device__ __forceinline__ void stage_tile(uint32_t tb, int pbase, int n,
                                                  int myidx, int tid,
                                                  const float4* __restrict__ f4) {
    #pragma unroll
    for (int k = 0; k < 2; k++) {
        const int s = tid + k * TPB;
        if (s < 512) {
            const int r = s >> 3, u = s & 7;
            const int p = pbase + r;
            const long rowc = (p < n) ? p : 0;
            cp16(tb + SWZ(r * 128 + u * 16), &f4[rowc * 8 + u], (p < n) ? 16u : 0u);
        }
    }
    const int g = tid >> 6, r = tid & 63;
    const uint32_t db = tb + (1 + g) * 8192;
    const long rowc = (myidx >= 0) ? myidx : 0;
    const uint32_t bytes = (myidx >= 0) ? 16u : 0u;
    #pragma unroll
    for (int u = 0; u < 8; u++)
        cp16(db + SWZ(r * 128 + u * 16), &f4[rowc * 8 + u], bytes);
}

__global__ __launch_bounds__(TPB, 1) void recon_kernel(
    const float* __restrict__ f,
    const int*   __restrict__ nbr_prev,
    const int*   __restrict__ nbr_next,
    const float* __restrict__ W,
    const float* __restrict__ gamma,
    const float* __restrict__ beta,
    const float* __restrict__ mean,
    const float* __restrict__ var,
    float* __restrict__ out, int n)
{
    extern __shared__ char smem[];
    const uint32_t sb = smem_u32(smem);
    const int tid  = threadIdx.x;
    const int lane = tid & 31;
    const int wid  = tid >> 5;
    const int rg   = wid & 3;        // row group (16 rows)
    const int br   = wid >> 2;       // branch 0..2

    float*    biasm = (float*)(smem + OFF_BIAS);
    uint32_t* Wsm   = (uint32_t*)(smem + OFF_W);

    // ---- fold BN into weights, tf32-round (RN), store [tap][cin row 128B][cout] ----
    for (int s = tid; s < 9216; s += TPB) {
        const int t9 = s >> 10;
        const int j  = s & 31;
        const int a  = (t9 >= 6) ? 2 : (t9 >= 3 ? 1 : 0);
        const float sc = gamma[a * 32 + j] * rsqrtf(var[a * 32 + j] + EPS_BN);
        Wsm[s] = cvt_tf32(W[s] * sc);
    }
    if (tid < 96) {
        const float sc = gamma[tid] * rsqrtf(var[tid] + EPS_BN);
        biasm[tid] = beta[tid] - mean[tid] * sc;
    }
    __syncthreads();

    // ---- preload this branch's B fragments (once per kernel) ----
    uint32_t breg[3][4][4][2];
    #pragma unroll
    for (int t = 0; t < 3; t++) {
        const uint32_t wb = sb + OFF_W + (br * 3 + t) * 4096;
        #pragma unroll
        for (int ks = 0; ks < 4; ks++)
            #pragma unroll
            for (int nc = 0; nc < 4; nc++) {
                const uint32_t a0 = wb + (ks * 8 + (lane & 3)) * 128 +
                                    (8 * nc + (lane >> 2)) * 4;
                breg[t][ks][nc][0] = lds32(a0);
                breg[t][ks][nc][1] = lds32(a0 + 4 * 128);
            }
    }

    const float4* __restrict__ f4 = (const float4*)f;
    const int ntiles = (n + TILE - 1) / TILE;
    const int grid = gridDim.x;

    // ---- prologue: stage first tile into buf0 ----
    int tile = blockIdx.x;
    {
        const int g = tid >> 6, a = g >> 1, r = tid & 63;
        const int p = tile * TILE + r;
        int idx = -1;
        if (tile < ntiles && p < n)
            idx = (g & 1) ? __ldg(&nbr_next[a * n + p]) : __ldg(&nbr_prev[a * n + p]);
        if (tile < ntiles) stage_tile(sb + OFF_T0, tile * TILE, n, idx, tid, f4);
        asm volatile("cp.async.commit_group;" ::: "memory");
    }

    const int r0  = rg * 16 + (lane >> 2);           // A base row within tile
    const int kb0 = (lane & 3) * 4;                  // A k-col byte offset
    const uint32_t swx  = (uint32_t)(((r0 * 128) >> 3) & 0x70);  // warp-const swizzle XOR
    const uint32_t abase = (uint32_t)(r0 * 128 + kb0);

    int cur = 0;
    for (; tile < ntiles; tile += grid) {
        asm volatile("cp.async.wait_group 0;" ::: "memory");
        __syncthreads();
        const uint32_t tb = sb + (cur ? OFF_T1 : OFF_T0);
        const int pbase = tile * TILE;
        const int ntile = tile + grid;

        // issue next tile's neighbor-index load early
        int nidx = -1;
        {
            const int g = tid >> 6, a = g >> 1, r = tid & 63;
            const int p = ntile * TILE + r;
            if (ntile < ntiles && p < n)
                nidx = (g & 1) ? __ldg(&nbr_next[a * n + p]) : __ldg(&nbr_prev[a * n + p]);
        }

        // group bases for this branch warp: t=0 prev, t=1 center, t=2 next
        uint32_t gbs[3];
        gbs[0] = tb + (1 + 2 * br) * 8192;
        gbs[1] = tb;
        gbs[2] = tb + (2 + 2 * br) * 8192;

        float acc[4][4];
        #pragma unroll
        for (int nc = 0; nc < 4; nc++) {
            const float2 b2 = *(const float2*)&biasm[br * 32 + 8 * nc + 2 * (lane & 3)];
            acc[nc][0] = acc[nc][2] = b2.x;
            acc[nc][1] = acc[nc][3] = b2.y;
        }

        // ---- software-pipelined 12-step MMA loop (raw fp32 -> tf32 truncation) ----
        uint32_t af[2][4];
        {
            const uint32_t u0 = gbs[0] + ((abase) ^ swx);
            const uint32_t u1 = gbs[0] + ((abase + 16) ^ swx);
            af[0][0] = lds32(u0);        af[0][1] = lds32(u0 + 1024);
            af[0][2] = lds32(u1);        af[0][3] = lds32(u1 + 1024);
        }
        #pragma unroll
        for (int s = 0; s < 12; s++) {
            const int pb = s & 1;
            if (s < 11) {
                const int s1 = s + 1;
                const uint32_t gb1 = gbs[s1 >> 2];
                const uint32_t o = abase + (uint32_t)((s1 & 3) * 32);
                const uint32_t u0 = gb1 + (o ^ swx);
                const uint32_t u1 = gb1 + ((o + 16) ^ swx);
                af[pb ^ 1][0] = lds32(u0);        af[pb ^ 1][1] = lds32(u0 + 1024);
                af[pb ^ 1][2] = lds32(u1);        af[pb ^ 1][3] = lds32(u1 + 1024);
            }
            const int t = s >> 2, ks = s & 3;
            #pragma unroll
            for (int nc = 0; nc < 4; nc++)
                mma_tf32(acc[nc], af[pb][0], af[pb][1], af[pb][2], af[pb][3],
                         breg[t][ks][nc][0], breg[t][ks][nc][1]);
        }

        // ---- stage next tile into other buffer ----
        if (ntile < ntiles)
            stage_tile(sb + (cur ? OFF_T0 : OFF_T1), ntile * TILE, n, nidx, tid, f4);
        asm volatile("cp.async.commit_group;" ::: "memory");

        // ---- sigmoid + partial store (conflict-free stride-40) ----
        #pragma unroll
        for (int nc = 0; nc < 4; nc++)
            #pragma unroll
            for (int rr = 0; rr < 2; rr++) {
                const int rowp = rg * 16 + (lane >> 2) + 8 * rr;
                const uint32_t addr = sb + OFF_R +
                    (((br * 64 + rowp) * RSTRIDE + 8 * nc + 2 * (lane & 3)) << 2);
                asm volatile("st.shared.v2.f32 [%0], {%1, %2};"
                             :: "r"(addr), "f"(sigmoid_fast(acc[nc][2 * rr])),
                                "f"(sigmoid_fast(acc[nc][2 * rr + 1])) : "memory");
            }
        __syncthreads();

        // ---- epilogue: sum 3 branches, gate by exact fp32 x, store ----
        #pragma unroll
        for (int k = 0; k < 2; k++) {
            const int s = tid + k * TPB;
            if (s < 512) {
                const int row = s >> 3, q = s & 7;
                const uint32_t rb = sb + OFF_R + ((row * RSTRIDE + 4 * q) << 2);
                const float4 s0 = lds128f(rb);
                const float4 s1 = lds128f(rb + 64 * RSTRIDE * 4);
                const float4 s2 = lds128f(rb + 128 * RSTRIDE * 4);
                const float4 x  = lds128f(tb + SWZ(row * 128 + q * 16));
                const int p = pbase + row;
                if (p < n) {
                    float4 v;
                    v.x = (s0.x + s1.x + s2.x) * x.x;
                    v.y = (s0.y + s1.y + s2.y) * x.y;
                    v.z = (s0.z + s1.z + s2.z) * x.z;
                    v.w = (s0.w + s1.w + s2.w) * x.w;
                    ((float4*)out)[(long)p * 8 + q] = v;
                }
            }
        }
        __syncthreads();
        cur ^= 1;
    }
}

extern "C" void kernel_launch(void* const* d_in, const int* in_sizes, int n_in,
                              void* d_out, int out_size) {
    const float* f     = (const float*)d_in[0];
    const int*   nprev = (const int*)  d_in[1];
    const int*   nnext = (const int*)  d_in[2];
    const float* W     = (const float*)d_in[3];
    const float* gamma = (const float*)d_in[4];
    const float* beta  = (const float*)d_in[5];
    const float* mean  = (const float*)d_in[6];
    const float* var   = (const float*)d_in[7];
    const int n = in_sizes[0] / 32;

    cudaFuncSetAttribute(recon_kernel, cudaFuncAttributeMaxDynamicSharedMemorySize,
                         SMEM_TOTAL);
    recon_kernel<<<148, TPB, SMEM_TOTAL>>>(f, nprev, nnext, W, gamma, beta, mean, var,
                                           (float*)d_out, n);
}

// round 10
// speedup vs baseline: 6.4443x; 1.1499x over previous
#include <cuda_runtime.h>
#include <cstdint>

#define TPB 192
#define TILE 32
#define EPS_BN 1e-5f
#define RSTRIDE 40

// smem byte offsets (per CTA, 108KB total -> 2 CTAs/SM)
#define OFF_BIAS 0                 // 96 floats
#define OFF_W    1024              // 9 taps * 4096B (32 k-rows x 128B, tf32-rounded fp32)
#define OFF_T0   37888             // 7 groups * 4096B (32 rows x 128B fp32, SWZ)
#define OFF_T1   66560
#define OFF_R    95232             // 3 * 32 * RSTRIDE * 4 = 15360
#define SMEM_TOTAL 110592

#define SWZ(o) ((o) ^ (((o) >> 3) & 0x70))

static __device__ __forceinline__ uint32_t smem_u32(const void* p) {
    uint32_t a;
    asm("{ .reg .u64 t; cvta.to.shared.u64 t, %1; cvt.u32.u64 %0, t; }" : "=r"(a) : "l"(p));
    return a;
}
static __device__ __forceinline__ uint32_t cvt_tf32(float x) {
    uint32_t r;
    asm("cvt.rna.tf32.f32 %0, %1;" : "=r"(r) : "f"(x));
    return r;
}
static __device__ __forceinline__ uint32_t lds32(uint32_t a) {
    uint32_t r;
    asm volatile("ld.shared.b32 %0, [%1];" : "=r"(r) : "r"(a));
    return r;
}
static __device__ __forceinline__ float4 lds128f(uint32_t a) {
    float4 v;
    asm volatile("ld.shared.v4.f32 {%0,%1,%2,%3}, [%4];"
                 : "=f"(v.x), "=f"(v.y), "=f"(v.z), "=f"(v.w) : "r"(a));
    return v;
}
static __device__ __forceinline__ void mma_tf32(float* d, uint32_t a0, uint32_t a1,
                                                uint32_t a2, uint32_t a3,
                                                uint32_t b0, uint32_t b1) {
    asm volatile("mma.sync.aligned.m16n8k8.row.col.f32.tf32.tf32.f32 "
                 "{%0,%1,%2,%3}, {%4,%5,%6,%7}, {%8,%9}, {%0,%1,%2,%3};"
                 : "+f"(d[0]), "+f"(d[1]), "+f"(d[2]), "+f"(d[3])
                 : "r"(a0), "r"(a1), "r"(a2), "r"(a3), "r"(b0), "r"(b1));
}
static __device__ __forceinline__ void cp16(uint32_t dst, const float4* src, uint32_t bytes) {
    const size_t g = __cvta_generic_to_global(src);
    asm volatile("cp.async.cg.shared.global [%0], [%1], 16, %2;"
                 :: "r"(dst), "l"(g), "r"(bytes) : "memory");
}
static __device__ __forceinline__ float sigmoid_fast(float v) {
    float th;
    asm("tanh.approx.f32 %0, %1;" : "=f"(th) : "f"(0.5f * v));
    return fmaf(th, 0.5f, 0.5f);
}

// stage one tile (center strided + this thread's neighbor row) into buffer tb
static __device__ __forceinline__ void stage_tile(uint32_t tb, int pbase, int n,
                                                  int myidx, int tid,
                                                  const float4* __restrict__ f4) {
    #pragma unroll
    for (int k = 0; k < 2; k++) {
        const int s = tid + k * TPB;
        if (s < 256) {
            const int r = s >> 3, u = s & 7;
            const int p = pbase + r;
            const long rowc = (p < n) ? p : 0;
            cp16(tb + SWZ(r * 128 + u * 16), &f4[rowc * 8 + u], (p < n) ? 16u : 0u);
        }
    }
    const int g = tid >> 5, r = tid & 31;       // 6 groups x 32 rows = 192 threads
    const uint32_t db = tb + (1 + g) * 4096;
    const long rowc = (myidx >= 0) ? myidx : 0;
    const uint32_t bytes = (myidx >= 0) ? 16u : 0u;
    #pragma unroll
    for (int u = 0; u < 8; u++)
        cp16(db + SWZ(r * 128 + u * 16), &f4[rowc * 8 + u], bytes);
}

__global__ __launch_bounds__(TPB, 2) void recon_kernel(
    const float* __restrict__ f,
    const int*   __restrict__ nbr_prev,
    const int*   __restrict__ nbr_next,
    const float* __restrict__ W,
    const float* __restrict__ gamma,
    const float* __restrict__ beta,
    const float* __restrict__ mean,
    const float* __restrict__ var,
    float* __restrict__ out, int n)
{
    extern __shared__ char smem[];
    const uint32_t sb = smem_u32(smem);
    const int tid  = threadIdx.x;
    const int lane = tid & 31;
    const int wid  = tid >> 5;
    const int rg   = wid & 1;        // row group (16 rows)
    const int br   = wid >> 1;       // branch 0..2

    float*    biasm = (float*)(smem + OFF_BIAS);
    uint32_t* Wsm   = (uint32_t*)(smem + OFF_W);

    // ---- fold BN into weights, tf32-round (RN), store [tap][cin row 128B][cout] ----
    for (int s = tid; s < 9216; s += TPB) {
        const int t9 = s >> 10;
        const int j  = s & 31;
        const int a  = (t9 >= 6) ? 2 : (t9 >= 3 ? 1 : 0);
        const float sc = gamma[a * 32 + j] * rsqrtf(var[a * 32 + j] + EPS_BN);
        Wsm[s] = cvt_tf32(W[s] * sc);
    }
    if (tid < 96) {
        const float sc = gamma[tid] * rsqrtf(var[tid] + EPS_BN);
        biasm[tid] = beta[tid] - mean[tid] * sc;
    }
    __syncthreads();

    // ---- preload this branch's B fragments (once per kernel) ----
    uint32_t breg[3][4][4][2];
    #pragma unroll
    for (int t = 0; t < 3; t++) {
        const uint32_t wb = sb + OFF_W + (br * 3 + t) * 4096;
        #pragma unroll
        for (int ks = 0; ks < 4; ks++)
            #pragma unroll
            for (int nc = 0; nc < 4; nc++) {
                const uint32_t a0 = wb + (ks * 8 + (lane & 3)) * 128 +
                                    (8 * nc + (lane >> 2)) * 4;
                breg[t][ks][nc][0] = lds32(a0);
                breg[t][ks][nc][1] = lds32(a0 + 4 * 128);
            }
    }

    const float4* __restrict__ f4 = (const float4*)f;
    const int ntiles = (n + TILE - 1) / TILE;
    const int grid = gridDim.x;

    // ---- prologue: stage first tile into buf0 ----
    int tile = blockIdx.x;
    {
        const int g = tid >> 5, a = g >> 1, r = tid & 31;
        const int p = tile * TILE + r;
        int idx = -1;
        if (tile < ntiles && p < n)
            idx = (g & 1) ? __ldg(&nbr_next[a * n + p]) : __ldg(&nbr_prev[a * n + p]);
        if (tile < ntiles) stage_tile(sb + OFF_T0, tile * TILE, n, idx, tid, f4);
        asm volatile("cp.async.commit_group;" ::: "memory");
    }

    const int r0  = rg * 16 + (lane >> 2);           // A base row within tile
    const int kb0 = (lane & 3) * 4;                  // A k-col byte offset
    const uint32_t swx   = (uint32_t)(((r0 * 128) >> 3) & 0x70);
    const uint32_t abase = (uint32_t)(r0 * 128 + kb0);

    int cur = 0;
    for (; tile < ntiles; tile += grid) {
        asm volatile("cp.async.wait_group 0;" ::: "memory");
        __syncthreads();
        const uint32_t tb = sb + (cur ? OFF_T1 : OFF_T0);
        const int pbase = tile * TILE;
        const int ntile = tile + grid;

        // issue next tile's neighbor-index load early
        int nidx = -1;
        {
            const int g = tid >> 5, a = g >> 1, r = tid & 31;
            const int p = ntile * TILE + r;
            if (ntile < ntiles && p < n)
                nidx = (g & 1) ? __ldg(&nbr_next[a * n + p]) : __ldg(&nbr_prev[a * n + p]);
        }

        uint32_t gbs[3];
        gbs[0] = tb + (1 + 2 * br) * 4096;
        gbs[1] = tb;
        gbs[2] = tb + (2 + 2 * br) * 4096;

        float acc[4][4];
        #pragma unroll
        for (int nc = 0; nc < 4; nc++) {
            const float2 b2 = *(const float2*)&biasm[br * 32 + 8 * nc + 2 * (lane & 3)];
            acc[nc][0] = acc[nc][2] = b2.x;
            acc[nc][1] = acc[nc][3] = b2.y;
        }

        // ---- software-pipelined 12-step MMA loop (fp32 regs -> tf32 MMA) ----
        uint32_t af[2][4];
        {
            const uint32_t u0 = gbs[0] + (abase ^ swx);
            const uint32_t u1 = gbs[0] + ((abase + 16) ^ swx);
            af[0][0] = lds32(u0);        af[0][1] = lds32(u0 + 1024);
            af[0][2] = lds32(u1);        af[0][3] = lds32(u1 + 1024);
        }
        #pragma unroll
        for (int s = 0; s < 12; s++) {
            const int pb = s & 1;
            if (s < 11) {
                const int s1 = s + 1;
                const uint32_t gb1 = gbs[s1 >> 2];
                const uint32_t o = abase + (uint32_t)((s1 & 3) * 32);
                const uint32_t u0 = gb1 + (o ^ swx);
                const uint32_t u1 = gb1 + ((o + 16) ^ swx);
                af[pb ^ 1][0] = lds32(u0);        af[pb ^ 1][1] = lds32(u0 + 1024);
                af[pb ^ 1][2] = lds32(u1);        af[pb ^ 1][3] = lds32(u1 + 1024);
            }
            const int t = s >> 2, ks = s & 3;
            #pragma unroll
            for (int nc = 0; nc < 4; nc++)
                mma_tf32(acc[nc], af[pb][0], af[pb][1], af[pb][2], af[pb][3],
                         breg[t][ks][nc][0], breg[t][ks][nc][1]);
        }

        // ---- stage next tile into other buffer ----
        if (ntile < ntiles)
            stage_tile(sb + (cur ? OFF_T0 : OFF_T1), ntile * TILE, n, nidx, tid, f4);
        asm volatile("cp.async.commit_group;" ::: "memory");

        // ---- sigmoid + partial store (conflict-free stride-40) ----
        #pragma unroll
        for (int nc = 0; nc < 4; nc++)
            #pragma unroll
            for (int rr = 0; rr < 2; rr++) {
                const int rowp = rg * 16 + (lane >> 2) + 8 * rr;
                const uint32_t addr = sb + OFF_R +
                    (((br * 32 + rowp) * RSTRIDE + 8 * nc + 2 * (lane & 3)) << 2);
                asm volatile("st.shared.v2.f32 [%0], {%1, %2};"
                             :: "r"(addr), "f"(sigmoid_fast(acc[nc][2 * rr])),
                                "f"(sigmoid_fast(acc[nc][2 * rr + 1])) : "memory");
            }
        __syncthreads();

        // ---- epilogue: sum 3 branches, gate by exact fp32 x, store ----
        #pragma unroll
        for (int k = 0; k < 2; k++) {
            const int s = tid + k * TPB;
            if (s < 256) {
                const int row = s >> 3, q = s & 7;
                const uint32_t rb = sb + OFF_R + ((row * RSTRIDE + 4 * q) << 2);
                const float4 s0 = lds128f(rb);
                const float4 s1 = lds128f(rb + 32 * RSTRIDE * 4);
                const float4 s2 = lds128f(rb + 64 * RSTRIDE * 4);
                const float4 x  = lds128f(tb + SWZ(row * 128 + q * 16));
                const int p = pbase + row;
                if (p < n) {
                    float4 v;
                    v.x = (s0.x + s1.x + s2.x) * x.x;
                    v.y = (s0.y + s1.y + s2.y) * x.y;
                    v.z = (s0.z + s1.z + s2.z) * x.z;
                    v.w = (s0.w + s1.w + s2.w) * x.w;
                    ((float4*)out)[(long)p * 8 + q] = v;
                }
            }
        }
        __syncthreads();
        cur ^= 1;
    }
}

extern "C" void kernel_launch(void* const* d_in, const int* in_sizes, int n_in,
                              void* d_out, int out_size) {
    const float* f     = (const float*)d_in[0];
    const int*   nprev = (const int*)  d_in[1];
    const int*   nnext = (const int*)  d_in[2];
    const float* W     = (const float*)d_in[3];
    const float* gamma = (const float*)d_in[4];
    const float* beta  = (const float*)d_in[5];
    const float* mean  = (const float*)d_in[6];
    const float* var   = (const float*)d_in[7];
    const int n = in_sizes[0] / 32;

    cudaFuncSetAttribute(recon_kernel, cudaFuncAttributeMaxDynamicSharedMemorySize,
                         SMEM_TOTAL);
    recon_kernel<<<296, TPB, SMEM_TOTAL>>>(f, nprev, nnext, W, gamma, beta, mean, var,
                                           (float*)d_out, n);
}

// round 11
// speedup vs baseline: 7.0532x; 1.0945x over previous
#include <cuda_runtime.h>
#include <cstdint>

#define TPB 96
#define TILE 16
#define EPS_BN 1e-5f
#define RSTRIDE 40

// smem byte offsets (per CTA, ~36.5KB -> 4 CTAs/SM, reg-bound)
#define OFF_BIAS 0                 // 96 floats
#define OFF_T0   1024              // 7 groups * 2048B (16 rows x 128B fp32, SWZ)
#define OFF_T1   15360
#define OFF_R    29696             // 3 * 16 * RSTRIDE * 4 = 7680
#define SMEM_TOTAL 37376

#define SWZ(o) ((o) ^ (((o) >> 3) & 0x70))

static __device__ __forceinline__ uint32_t smem_u32(const void* p) {
    uint32_t a;
    asm("{ .reg .u64 t; cvta.to.shared.u64 t, %1; cvt.u32.u64 %0, t; }" : "=r"(a) : "l"(p));
    return a;
}
static __device__ __forceinline__ uint32_t cvt_tf32(float x) {
    uint32_t r;
    asm("cvt.rna.tf32.f32 %0, %1;" : "=r"(r) : "f"(x));
    return r;
}
static __device__ __forceinline__ uint32_t lds32(uint32_t a) {
    uint32_t r;
    asm volatile("ld.shared.b32 %0, [%1];" : "=r"(r) : "r"(a));
    return r;
}
static __device__ __forceinline__ float4 lds128f(uint32_t a) {
    float4 v;
    asm volatile("ld.shared.v4.f32 {%0,%1,%2,%3}, [%4];"
                 : "=f"(v.x), "=f"(v.y), "=f"(v.z), "=f"(v.w) : "r"(a));
    return v;
}
static __device__ __forceinline__ void mma_tf32(float* d, uint32_t a0, uint32_t a1,
                                                uint32_t a2, uint32_t a3,
                                                uint32_t b0, uint32_t b1) {
    asm volatile("mma.sync.aligned.m16n8k8.row.col.f32.tf32.tf32.f32 "
                 "{%0,%1,%2,%3}, {%4,%5,%6,%7}, {%8,%9}, {%0,%1,%2,%3};"
                 : "+f"(d[0]), "+f"(d[1]), "+f"(d[2]), "+f"(d[3])
                 : "r"(a0), "r"(a1), "r"(a2), "r"(a3), "r"(b0), "r"(b1));
}
static __device__ __forceinline__ void cp16(uint32_t dst, const float4* src, uint32_t bytes) {
    const size_t g = __cvta_generic_to_global(src);
    asm volatile("cp.async.cg.shared.global [%0], [%1], 16, %2;"
                 :: "r"(dst), "l"(g), "r"(bytes) : "memory");
}
static __device__ __forceinline__ float sigmoid_fast(float v) {
    float th;
    asm("tanh.approx.f32 %0, %1;" : "=f"(th) : "f"(0.5f * v));
    return fmaf(th, 0.5f, 0.5f);
}

// stage one tile (center + this thread's neighbor row) into buffer tb
static __device__ __forceinline__ void stage_tile(uint32_t tb, int pbase, int n,
                                                  int myidx, int tid,
                                                  const float4* __restrict__ f4) {
    #pragma unroll
    for (int k = 0; k < 2; k++) {
        const int s = tid + k * TPB;
        if (s < 128) {
            const int r = s >> 3, u = s & 7;
            const int p = pbase + r;
            const long rowc = (p < n) ? p : 0;
            cp16(tb + SWZ(r * 128 + u * 16), &f4[rowc * 8 + u], (p < n) ? 16u : 0u);
        }
    }
    const int g = tid >> 4, r = tid & 15;       // 6 groups x 16 rows = 96 threads
    const uint32_t db = tb + (1 + g) * 2048;
    const long rowc = (myidx >= 0) ? myidx : 0;
    const uint32_t bytes = (myidx >= 0) ? 16u : 0u;
    #pragma unroll
    for (int u = 0; u < 8; u++)
        cp16(db + SWZ(r * 128 + u * 16), &f4[rowc * 8 + u], bytes);
}

__global__ __launch_bounds__(TPB, 4) void recon_kernel(
    const float* __restrict__ f,
    const int*   __restrict__ nbr_prev,
    const int*   __restrict__ nbr_next,
    const float* __restrict__ W,
    const float* __restrict__ gamma,
    const float* __restrict__ beta,
    const float* __restrict__ mean,
    const float* __restrict__ var,
    float* __restrict__ out, int n)
{
    extern __shared__ char smem[];
    const uint32_t sb = smem_u32(smem);
    const int tid  = threadIdx.x;
    const int lane = tid & 31;
    const int br   = tid >> 5;       // branch 0..2 (one warp per branch)

    float* biasm = (float*)(smem + OFF_BIAS);

    if (tid < 96) {
        const float sc = gamma[tid] * rsqrtf(var[tid] + EPS_BN);
        biasm[tid] = beta[tid] - mean[tid] * sc;
    }
    __syncthreads();

    // ---- build this branch's B fragments directly from global W (BN folded) ----
    uint32_t breg[3][4][4][2];
    {
        float scj[4];
        #pragma unroll
        for (int nc = 0; nc < 4; nc++) {
            const int j = 8 * nc + (lane >> 2);
            scj[nc] = gamma[br * 32 + j] * rsqrtf(var[br * 32 + j] + EPS_BN);
        }
        #pragma unroll
        for (int t = 0; t < 3; t++) {
            const float* Wt = W + (br * 3 + t) * 1024;
            #pragma unroll
            for (int ks = 0; ks < 4; ks++) {
                const int i = ks * 8 + (lane & 3);
                #pragma unroll
                for (int nc = 0; nc < 4; nc++) {
                    const int j = 8 * nc + (lane >> 2);
                    breg[t][ks][nc][0] = cvt_tf32(__ldg(&Wt[i * 32 + j]) * scj[nc]);
                    breg[t][ks][nc][1] = cvt_tf32(__ldg(&Wt[(i + 4) * 32 + j]) * scj[nc]);
                }
            }
        }
    }

    const float4* __restrict__ f4 = (const float4*)f;
    const int ntiles = (n + TILE - 1) / TILE;
    const int grid = gridDim.x;

    // ---- prologue: stage first tile into buf0 ----
    int tile = blockIdx.x;
    {
        const int g = tid >> 4, a = g >> 1, r = tid & 15;
        const int p = tile * TILE + r;
        int idx = -1;
        if (tile < ntiles && p < n)
            idx = (g & 1) ? __ldg(&nbr_next[a * n + p]) : __ldg(&nbr_prev[a * n + p]);
        if (tile < ntiles) stage_tile(sb + OFF_T0, tile * TILE, n, idx, tid, f4);
        asm volatile("cp.async.commit_group;" ::: "memory");
    }

    const int r0  = lane >> 2;                       // A base row within 16-row tile
    const int kb0 = (lane & 3) * 4;                  // A k-col byte offset
    const uint32_t swx   = (uint32_t)(((r0 * 128) >> 3) & 0x70);
    const uint32_t abase = (uint32_t)(r0 * 128 + kb0);

    int cur = 0;
    for (; tile < ntiles; tile += grid) {
        asm volatile("cp.async.wait_group 0;" ::: "memory");
        __syncthreads();
        const uint32_t tb = sb + (cur ? OFF_T1 : OFF_T0);
        const int pbase = tile * TILE;
        const int ntile = tile + grid;

        // issue next tile's neighbor-index load early
        int nidx = -1;
        {
            const int g = tid >> 4, a = g >> 1, r = tid & 15;
            const int p = ntile * TILE + r;
            if (ntile < ntiles && p < n)
                nidx = (g & 1) ? __ldg(&nbr_next[a * n + p]) : __ldg(&nbr_prev[a * n + p]);
        }

        uint32_t gbs[3];
        gbs[0] = tb + (1 + 2 * br) * 2048;
        gbs[1] = tb;
        gbs[2] = tb + (2 + 2 * br) * 2048;

        float acc[4][4];
        #pragma unroll
        for (int nc = 0; nc < 4; nc++) {
            const float2 b2 = *(const float2*)&biasm[br * 32 + 8 * nc + 2 * (lane & 3)];
            acc[nc][0] = acc[nc][2] = b2.x;
            acc[nc][1] = acc[nc][3] = b2.y;
        }

        // ---- software-pipelined 12-step MMA loop (fp32 regs -> tf32 MMA) ----
        uint32_t af[2][4];
        {
            const uint32_t u0 = gbs[0] + (abase ^ swx);
            const uint32_t u1 = gbs[0] + ((abase + 16) ^ swx);
            af[0][0] = lds32(u0);        af[0][1] = lds32(u0 + 1024);
            af[0][2] = lds32(u1);        af[0][3] = lds32(u1 + 1024);
        }
        #pragma unroll
        for (int s = 0; s < 12; s++) {
            const int pb = s & 1;
            if (s < 11) {
                const int s1 = s + 1;
                const uint32_t gb1 = gbs[s1 >> 2];
                const uint32_t o = abase + (uint32_t)((s1 & 3) * 32);
                const uint32_t u0 = gb1 + (o ^ swx);
                const uint32_t u1 = gb1 + ((o + 16) ^ swx);
                af[pb ^ 1][0] = lds32(u0);        af[pb ^ 1][1] = lds32(u0 + 1024);
                af[pb ^ 1][2] = lds32(u1);        af[pb ^ 1][3] = lds32(u1 + 1024);
            }
            const int t = s >> 2, ks = s & 3;
            #pragma unroll
            for (int nc = 0; nc < 4; nc++)
                mma_tf32(acc[nc], af[pb][0], af[pb][1], af[pb][2], af[pb][3],
                         breg[t][ks][nc][0], breg[t][ks][nc][1]);
        }

        // ---- stage next tile into other buffer ----
        if (ntile < ntiles)
            stage_tile(sb + (cur ? OFF_T0 : OFF_T1), ntile * TILE, n, nidx, tid, f4);
        asm volatile("cp.async.commit_group;" ::: "memory");

        // ---- sigmoid + partial store (stride-40 reduction buffer) ----
        #pragma unroll
        for (int nc = 0; nc < 4; nc++)
            #pragma unroll
            for (int rr = 0; rr < 2; rr++) {
                const int rowp = (lane >> 2) + 8 * rr;
                const uint32_t addr = sb + OFF_R +
                    (((br * 16 + rowp) * RSTRIDE + 8 * nc + 2 * (lane & 3)) << 2);
                asm volatile("st.shared.v2.f32 [%0], {%1, %2};"
                             :: "r"(addr), "f"(sigmoid_fast(acc[nc][2 * rr])),
                                "f"(sigmoid_fast(acc[nc][2 * rr + 1])) : "memory");
            }
        __syncthreads();

        // ---- epilogue: sum 3 branches, gate by exact fp32 x, store ----
        #pragma unroll
        for (int k = 0; k < 2; k++) {
            const int s = tid + k * TPB;
            if (s < 128) {
                const int row = s >> 3, q = s & 7;
                const uint32_t rb = sb + OFF_R + ((row * RSTRIDE + 4 * q) << 2);
                const float4 s0 = lds128f(rb);
                const float4 s1 = lds128f(rb + 16 * RSTRIDE * 4);
                const float4 s2 = lds128f(rb + 32 * RSTRIDE * 4);
                const float4 x  = lds128f(tb + SWZ(row * 128 + q * 16));
                const int p = pbase + row;
                if (p < n) {
                    float4 v;
                    v.x = (s0.x + s1.x + s2.x) * x.x;
                    v.y = (s0.y + s1.y + s2.y) * x.y;
                    v.z = (s0.z + s1.z + s2.z) * x.z;
                    v.w = (s0.w + s1.w + s2.w) * x.w;
                    ((float4*)out)[(long)p * 8 + q] = v;
                }
            }
        }
        __syncthreads();
        cur ^= 1;
    }
}

extern "C" void kernel_launch(void* const* d_in, const int* in_sizes, int n_in,
                              void* d_out, int out_size) {
    const float* f     = (const float*)d_in[0];
    const int*   nprev = (const int*)  d_in[1];
    const int*   nnext = (const int*)  d_in[2];
    const float* W     = (const float*)d_in[3];
    const float* gamma = (const float*)d_in[4];
    const float* beta  = (const float*)d_in[5];
    const float* mean  = (const float*)d_in[6];
    const float* var   = (const float*)d_in[7];
    const int n = in_sizes[0] / 32;

    cudaFuncSetAttribute(recon_kernel, cudaFuncAttributeMaxDynamicSharedMemorySize,
                         SMEM_TOTAL);
    recon_kernel<<<592, TPB, SMEM_TOTAL>>>(f, nprev, nnext, W, gamma, beta, mean, var,
                                           (float*)d_out, n);
}

// round 12
// speedup vs baseline: 8.1521x; 1.1558x over previous
#include <cuda_runtime.h>
#include <cstdint>

#define TPB 96
#define TILE 16
#define EPS_BN 1e-5f
#define RSTRIDE 40

// smem byte offsets (per CTA, ~36.5KB -> 4 CTAs/SM, reg-bound)
#define OFF_BIAS 0                 // 96 floats
#define OFF_T0   1024              // 7 groups * 2048B (16 rows x 128B fp32, SWZ)
#define OFF_T1   15360
#define OFF_R    29696             // 3 * 16 * RSTRIDE * 4 = 7680
#define SMEM_TOTAL 37376
#define DBUF (OFF_T1 - OFF_T0)

#define SWZ(o) ((o) ^ (((o) >> 3) & 0x70))

static __device__ __forceinline__ uint32_t smem_u32(const void* p) {
    uint32_t a;
    asm("{ .reg .u64 t; cvta.to.shared.u64 t, %1; cvt.u32.u64 %0, t; }" : "=r"(a) : "l"(p));
    return a;
}
static __device__ __forceinline__ uint32_t cvt_tf32(float x) {
    uint32_t r;
    asm("cvt.rna.tf32.f32 %0, %1;" : "=r"(r) : "f"(x));
    return r;
}
static __device__ __forceinline__ uint32_t lds32(uint32_t a) {
    uint32_t r;
    asm volatile("ld.shared.b32 %0, [%1];" : "=r"(r) : "r"(a));
    return r;
}
static __device__ __forceinline__ float4 lds128f(uint32_t a) {
    float4 v;
    asm volatile("ld.shared.v4.f32 {%0,%1,%2,%3}, [%4];"
                 : "=f"(v.x), "=f"(v.y), "=f"(v.z), "=f"(v.w) : "r"(a));
    return v;
}
static __device__ __forceinline__ void mma_tf32(float* d, uint32_t a0, uint32_t a1,
                                                uint32_t a2, uint32_t a3,
                                                uint32_t b0, uint32_t b1) {
    asm volatile("mma.sync.aligned.m16n8k8.row.col.f32.tf32.tf32.f32 "
                 "{%0,%1,%2,%3}, {%4,%5,%6,%7}, {%8,%9}, {%0,%1,%2,%3};"
                 : "+f"(d[0]), "+f"(d[1]), "+f"(d[2]), "+f"(d[3])
                 : "r"(a0), "r"(a1), "r"(a2), "r"(a3), "r"(b0), "r"(b1));
}
static __device__ __forceinline__ void cp16(uint32_t dst, const float4* src, uint32_t bytes) {
    const size_t g = __cvta_generic_to_global(src);
    asm volatile("cp.async.cg.shared.global [%0], [%1], 16, %2;"
                 :: "r"(dst), "l"(g), "r"(bytes) : "memory");
}
static __device__ __forceinline__ float sigmoid_fast(float v) {
    float th;
    asm("tanh.approx.f32 %0, %1;" : "=f"(th) : "f"(0.5f * v));
    return fmaf(th, 0.5f, 0.5f);
}

__global__ __launch_bounds__(TPB, 4) void recon_kernel(
    const float* __restrict__ f,
    const int*   __restrict__ nbr_prev,
    const int*   __restrict__ nbr_next,
    const float* __restrict__ W,
    const float* __restrict__ gamma,
    const float* __restrict__ beta,
    const float* __restrict__ mean,
    const float* __restrict__ var,
    float* __restrict__ out, int n)
{
    extern __shared__ char smem[];
    const uint32_t sb = smem_u32(smem);
    const int tid  = threadIdx.x;
    const int lane = tid & 31;
    const int br   = tid >> 5;       // branch 0..2 (one warp per branch)

    float* biasm = (float*)(smem + OFF_BIAS);

    if (tid < 96) {
        const float sc = gamma[tid] * rsqrtf(var[tid] + EPS_BN);
        biasm[tid] = beta[tid] - mean[tid] * sc;
    }
    __syncthreads();

    // ---- build this branch's B fragments directly from global W (BN folded) ----
    uint32_t breg[3][4][4][2];
    {
        float scj[4];
        #pragma unroll
        for (int nc = 0; nc < 4; nc++) {
            const int j = 8 * nc + (lane >> 2);
            scj[nc] = gamma[br * 32 + j] * rsqrtf(var[br * 32 + j] + EPS_BN);
        }
        #pragma unroll
        for (int t = 0; t < 3; t++) {
            const float* Wt = W + (br * 3 + t) * 1024;
            #pragma unroll
            for (int ks = 0; ks < 4; ks++) {
                const int i = ks * 8 + (lane & 3);
                #pragma unroll
                for (int nc = 0; nc < 4; nc++) {
                    const int j = 8 * nc + (lane >> 2);
                    breg[t][ks][nc][0] = cvt_tf32(__ldg(&Wt[i * 32 + j]) * scj[nc]);
                    breg[t][ks][nc][1] = cvt_tf32(__ldg(&Wt[(i + 4) * 32 + j]) * scj[nc]);
                }
            }
        }
    }

    const float4* __restrict__ f4 = (const float4*)f;
    const int ntiles = (n + TILE - 1) / TILE;
    const int grid = gridDim.x;

    // ---- per-thread staging geometry (constant across tiles) ----
    const int gst  = tid >> 4;               // neighbor group 0..5
    const int ast  = gst >> 1;               // axis
    const bool isnext = (gst & 1);
    const int rstn = tid & 15;               // neighbor row
    const int rc0 = tid >> 3, uc0 = tid & 7; // center part A (s = tid, always <128)
    const int s1  = tid + TPB;
    const bool c1v = (s1 < 128);             // center part B (threads 0..31)
    const int rc1 = s1 >> 3, uc1 = s1 & 7;
    const uint32_t dstc0 = OFF_T0 + SWZ((uint32_t)(rc0 * 128 + uc0 * 16));
    const uint32_t dstc1 = OFF_T0 + SWZ((uint32_t)(rc1 * 128 + uc1 * 16));
    uint32_t dstn[8];
    #pragma unroll
    for (int u = 0; u < 8; u++)
        dstn[u] = OFF_T0 + (1 + gst) * 2048 + SWZ((uint32_t)(rstn * 128 + u * 16));

    // ---- MMA per-lane geometry ----
    const int r0  = lane >> 2;
    const int kb0 = (lane & 3) * 4;
    const uint32_t swx   = (uint32_t)(((r0 * 128) >> 3) & 0x70);
    const uint32_t abase = (uint32_t)(r0 * 128 + kb0);

    // ---- prologue: stage tile0 into buf0; prefetch idx for tile1 ----
    int tile = blockIdx.x;
    {
        const int p = tile * TILE + rstn;
        int idx = -1;
        if (tile < ntiles && p < n)
            idx = isnext ? __ldg(&nbr_next[ast * n + p]) : __ldg(&nbr_prev[ast * n + p]);
        if (tile < ntiles) {
            const int pbase = tile * TILE;
            { const int pc = pbase + rc0;
              cp16(sb + dstc0, &f4[(long)(pc < n ? pc : 0) * 8 + uc0], pc < n ? 16u : 0u); }
            if (c1v) { const int pc = pbase + rc1;
              cp16(sb + dstc1, &f4[(long)(pc < n ? pc : 0) * 8 + uc1], pc < n ? 16u : 0u); }
            const long rowc = (idx >= 0) ? idx : 0;
            const uint32_t bytes = (idx >= 0) ? 16u : 0u;
            #pragma unroll
            for (int u = 0; u < 8; u++)
                cp16(sb + dstn[u], &f4[rowc * 8 + u], bytes);
        }
        asm volatile("cp.async.commit_group;" ::: "memory");
    }
    int pidx1;
    {
        const int t1 = tile + grid;
        const int p = t1 * TILE + rstn;
        pidx1 = -1;
        if (t1 < ntiles && p < n)
            pidx1 = isnext ? __ldg(&nbr_next[ast * n + p]) : __ldg(&nbr_prev[ast * n + p]);
    }

    int cur = 0;
    for (; tile < ntiles; tile += grid) {
        asm volatile("cp.async.wait_group 0;" ::: "memory");
        __syncthreads();
        const uint32_t bufadd = cur ? (uint32_t)DBUF : 0u;
        const uint32_t tb = sb + OFF_T0 + bufadd;
        const int pbase = tile * TILE;
        const int ntile = tile + grid;

        // ---- stage tile t+1 NOW (latency covered by MMA+epilogue below) ----
        if (ntile < ntiles) {
            const uint32_t oadd = cur ? 0u : (uint32_t)DBUF;
            const int npb = ntile * TILE;
            { const int pc = npb + rc0;
              cp16(sb + dstc0 + oadd, &f4[(long)(pc < n ? pc : 0) * 8 + uc0], pc < n ? 16u : 0u); }
            if (c1v) { const int pc = npb + rc1;
              cp16(sb + dstc1 + oadd, &f4[(long)(pc < n ? pc : 0) * 8 + uc1], pc < n ? 16u : 0u); }
            const long rowc = (pidx1 >= 0) ? pidx1 : 0;
            const uint32_t bytes = (pidx1 >= 0) ? 16u : 0u;
            #pragma unroll
            for (int u = 0; u < 8; u++)
                cp16(sb + dstn[u] + oadd, &f4[rowc * 8 + u], bytes);
        }
        asm volatile("cp.async.commit_group;" ::: "memory");

        // ---- prefetch idx for tile t+2 (LDG covered by MMA) ----
        int pidx2 = -1;
        {
            const int t2 = ntile + grid;
            const int p = t2 * TILE + rstn;
            if (t2 < ntiles && p < n)
                pidx2 = isnext ? __ldg(&nbr_next[ast * n + p]) : __ldg(&nbr_prev[ast * n + p]);
        }

        uint32_t gbs[3];
        gbs[0] = tb + (1 + 2 * br) * 2048;
        gbs[1] = tb;
        gbs[2] = tb + (2 + 2 * br) * 2048;

        float acc[4][4];
        #pragma unroll
        for (int nc = 0; nc < 4; nc++) {
            const float2 b2 = *(const float2*)&biasm[br * 32 + 8 * nc + 2 * (lane & 3)];
            acc[nc][0] = acc[nc][2] = b2.x;
            acc[nc][1] = acc[nc][3] = b2.y;
        }

        // ---- software-pipelined 12-step MMA loop (fp32 regs -> tf32 MMA) ----
        uint32_t af[2][4];
        {
            const uint32_t u0 = gbs[0] + (abase ^ swx);
            const uint32_t u1 = gbs[0] + ((abase + 16) ^ swx);
            af[0][0] = lds32(u0);        af[0][1] = lds32(u0 + 1024);
            af[0][2] = lds32(u1);        af[0][3] = lds32(u1 + 1024);
        }
        #pragma unroll
        for (int s = 0; s < 12; s++) {
            const int pb = s & 1;
            if (s < 11) {
                const int s1s = s + 1;
                const uint32_t gb1 = gbs[s1s >> 2];
                const uint32_t o = abase + (uint32_t)((s1s & 3) * 32);
                const uint32_t u0 = gb1 + (o ^ swx);
                const uint32_t u1 = gb1 + ((o + 16) ^ swx);
                af[pb ^ 1][0] = lds32(u0);        af[pb ^ 1][1] = lds32(u0 + 1024);
                af[pb ^ 1][2] = lds32(u1);        af[pb ^ 1][3] = lds32(u1 + 1024);
            }
            const int t = s >> 2, ks = s & 3;
            #pragma unroll
            for (int nc = 0; nc < 4; nc++)
                mma_tf32(acc[nc], af[pb][0], af[pb][1], af[pb][2], af[pb][3],
                         breg[t][ks][nc][0], breg[t][ks][nc][1]);
        }

        // ---- sigmoid + partial store (stride-40 reduction buffer) ----
        #pragma unroll
        for (int nc = 0; nc < 4; nc++)
            #pragma unroll
            for (int rr = 0; rr < 2; rr++) {
                const int rowp = (lane >> 2) + 8 * rr;
                const uint32_t addr = sb + OFF_R +
                    (((br * 16 + rowp) * RSTRIDE + 8 * nc + 2 * (lane & 3)) << 2);
                asm volatile("st.shared.v2.f32 [%0], {%1, %2};"
                             :: "r"(addr), "f"(sigmoid_fast(acc[nc][2 * rr])),
                                "f"(sigmoid_fast(acc[nc][2 * rr + 1])) : "memory");
            }
        __syncthreads();

        // ---- epilogue: sum 3 branches, gate by exact fp32 x, store ----
        #pragma unroll
        for (int k = 0; k < 2; k++) {
            const int s = tid + k * TPB;
            if (s < 128) {
                const int row = s >> 3, q = s & 7;
                const uint32_t rb = sb + OFF_R + ((row * RSTRIDE + 4 * q) << 2);
                const float4 s0 = lds128f(rb);
                const float4 s1v = lds128f(rb + 16 * RSTRIDE * 4);
                const float4 s2 = lds128f(rb + 32 * RSTRIDE * 4);
                const float4 x  = lds128f(tb + SWZ((uint32_t)(row * 128 + q * 16)));
                const int p = pbase + row;
                if (p < n) {
                    float4 v;
                    v.x = (s0.x + s1v.x + s2.x) * x.x;
                    v.y = (s0.y + s1v.y + s2.y) * x.y;
                    v.z = (s0.z + s1v.z + s2.z) * x.z;
                    v.w = (s0.w + s1v.w + s2.w) * x.w;
                    ((float4*)out)[(long)p * 8 + q] = v;
                }
            }
        }
        pidx1 = pidx2;
        cur ^= 1;
        // no trailing barrier: next iteration's loop-top __syncthreads orders
        // all cross-iteration smem dependencies (R writes, buffer reuse)
    }
}

extern "C" void kernel_launch(void* const* d_in, const int* in_sizes, int n_in,
                              void* d_out, int out_size) {
    const float* f     = (const float*)d_in[0];
    const int*   nprev = (const int*)  d_in[1];
    const int*   nnext = (const int*)  d_in[2];
    const float* W     = (const float*)d_in[3];
    const float* gamma = (const float*)d_in[4];
    const float* beta  = (const float*)d_in[5];
    const float* mean  = (const float*)d_in[6];
    const float* var   = (const float*)d_in[7];
    const int n = in_sizes[0] / 32;

    cudaFuncSetAttribute(recon_kernel, cudaFuncAttributeMaxDynamicSharedMemorySize,
                         SMEM_TOTAL);
    recon_kernel<<<592, TPB, SMEM_TOTAL>>>(f, nprev, nnext, W, gamma, beta, mean, var,
                                           (float*)d_out, n);
}

// round 14
// speedup vs baseline: 8.7202x; 1.0697x over previous
#include <cuda_runtime.h>
#include <cstdint>

#define TPB 96
#define TILE 16
#define EPS_BN 1e-5f
#define RSTRIDE 40

// smem byte offsets (per CTA, ~36.5KB -> 4 CTAs/SM, reg-bound)
#define OFF_BIAS 0                 // 96 floats
#define OFF_T0   1024              // 7 groups * 2048B (16 rows x 128B fp32, SWZ)
#define OFF_T1   15360
#define OFF_R    29696             // 3 * 16 * RSTRIDE * 4 = 7680
#define SMEM_TOTAL 37376
#define DBUF (OFF_T1 - OFF_T0)

#define SWZ(o) ((o) ^ (((o) >> 3) & 0x70))

static __device__ __forceinline__ uint32_t smem_u32(const void* p) {
    uint32_t a;
    asm("{ .reg .u64 t; cvta.to.shared.u64 t, %1; cvt.u32.u64 %0, t; }" : "=r"(a) : "l"(p));
    return a;
}
static __device__ __forceinline__ uint32_t cvt_tf32(float x) {
    uint32_t r;
    asm("cvt.rna.tf32.f32 %0, %1;" : "=r"(r) : "f"(x));
    return r;
}
static __device__ __forceinline__ float4 lds128f(uint32_t a) {
    float4 v;
    asm volatile("ld.shared.v4.f32 {%0,%1,%2,%3}, [%4];"
                 : "=f"(v.x), "=f"(v.y), "=f"(v.z), "=f"(v.w) : "r"(a));
    return v;
}
static __device__ __forceinline__ void ldsm4(uint32_t* r, uint32_t addr) {
    asm volatile("ldmatrix.sync.aligned.m8n8.x4.shared.b16 {%0,%1,%2,%3}, [%4];"
                 : "=r"(r[0]), "=r"(r[1]), "=r"(r[2]), "=r"(r[3]) : "r"(addr));
}
static __device__ __forceinline__ void mma_tf32(float* d, uint32_t a0, uint32_t a1,
                                                uint32_t a2, uint32_t a3,
                                                uint32_t b0, uint32_t b1) {
    asm volatile("mma.sync.aligned.m16n8k8.row.col.f32.tf32.tf32.f32 "
                 "{%0,%1,%2,%3}, {%4,%5,%6,%7}, {%8,%9}, {%0,%1,%2,%3};"
                 : "+f"(d[0]), "+f"(d[1]), "+f"(d[2]), "+f"(d[3])
                 : "r"(a0), "r"(a1), "r"(a2), "r"(a3), "r"(b0), "r"(b1));
}
static __device__ __forceinline__ void cp16(uint32_t dst, const float4* src, uint32_t bytes) {
    const size_t g = __cvta_generic_to_global(src);
    asm volatile("cp.async.cg.shared.global [%0], [%1], 16, %2;"
                 :: "r"(dst), "l"(g), "r"(bytes) : "memory");
}
// 8 copies of one 128B row with a single base register + immediate offsets
static __device__ __forceinline__ void cp16x8(uint32_t d0, uint32_t d1, uint32_t d2,
                                              uint32_t d3, uint32_t d4, uint32_t d5,
                                              uint32_t d6, uint32_t d7,
                                              const float4* src, uint32_t bytes) {
    const size_t g = __cvta_generic_to_global(src);
    asm volatile(
        "cp.async.cg.shared.global [%0], [%8+0],   16, %9;\n\t"
        "cp.async.cg.shared.global [%1], [%8+16],  16, %9;\n\t"
        "cp.async.cg.shared.global [%2], [%8+32],  16, %9;\n\t"
        "cp.async.cg.shared.global [%3], [%8+48],  16, %9;\n\t"
        "cp.async.cg.shared.global [%4], [%8+64],  16, %9;\n\t"
        "cp.async.cg.shared.global [%5], [%8+80],  16, %9;\n\t"
        "cp.async.cg.shared.global [%6], [%8+96],  16, %9;\n\t"
        "cp.async.cg.shared.global [%7], [%8+112], 16, %9;\n\t"
        :: "r"(d0), "r"(d1), "r"(d2), "r"(d3), "r"(d4), "r"(d5), "r"(d6), "r"(d7),
           "l"(g), "r"(bytes) : "memory");
}
static __device__ __forceinline__ float sigmoid_fast(float v) {
    float th;
    asm("tanh.approx.f32 %0, %1;" : "=f"(th) : "f"(0.5f * v));
    return fmaf(th, 0.5f, 0.5f);
}

__global__ __launch_bounds__(TPB, 4) void recon_kernel(
    const float* __restrict__ f,
    const int*   __restrict__ nbr_prev,
    const int*   __restrict__ nbr_next,
    const float* __restrict__ W,
    const float* __restrict__ gamma,
    const float* __restrict__ beta,
    const float* __restrict__ mean,
    const float* __restrict__ var,
    float* __restrict__ out, int n)
{
    extern __shared__ char smem[];
    const uint32_t sb = smem_u32(smem);
    const int tid  = threadIdx.x;
    const int lane = tid & 31;
    const int br   = tid >> 5;       // branch 0..2 (one warp per branch)

    float* biasm = (float*)(smem + OFF_BIAS);

    if (tid < 96) {
        const float sc = gamma[tid] * rsqrtf(var[tid] + EPS_BN);
        biasm[tid] = beta[tid] - mean[tid] * sc;
    }
    __syncthreads();

    // ---- build this branch's B fragments directly from global W (BN folded) ----
    uint32_t breg[3][4][4][2];
    {
        float scj[4];
        #pragma unroll
        for (int nc = 0; nc < 4; nc++) {
            const int j = 8 * nc + (lane >> 2);
            scj[nc] = gamma[br * 32 + j] * rsqrtf(var[br * 32 + j] + EPS_BN);
        }
        #pragma unroll
        for (int t = 0; t < 3; t++) {
            const float* Wt = W + (br * 3 + t) * 1024;
            #pragma unroll
            for (int ks = 0; ks < 4; ks++) {
                const int i = ks * 8 + (lane & 3);
                #pragma unroll
                for (int nc = 0; nc < 4; nc++) {
                    const int j = 8 * nc + (lane >> 2);
                    breg[t][ks][nc][0] = cvt_tf32(__ldg(&Wt[i * 32 + j]) * scj[nc]);
                    breg[t][ks][nc][1] = cvt_tf32(__ldg(&Wt[(i + 4) * 32 + j]) * scj[nc]);
                }
            }
        }
    }

    const float4* __restrict__ f4 = (const float4*)f;
    const int ntiles = (n + TILE - 1) / TILE;
    const int grid = gridDim.x;

    // ---- per-thread staging geometry (constant across tiles) ----
    const int gst  = tid >> 4;               // neighbor group 0..5
    const int ast  = gst >> 1;               // axis
    const bool isnext = (gst & 1);
    const int rstn = tid & 15;               // neighbor row
    const int rc0 = tid >> 3, uc0 = tid & 7; // center part A (rows 0..11)
    const int s1  = tid + TPB;
    const bool c1v = (s1 < 128);             // center part B (threads 0..31)
    const int rc1 = s1 >> 3, uc1 = s1 & 7;
    const uint32_t dstc0 = OFF_T0 + SWZ((uint32_t)(rc0 * 128 + uc0 * 16));
    const uint32_t dstc1 = OFF_T0 + SWZ((uint32_t)(rc1 * 128 + uc1 * 16));
    uint32_t dstn[8];
    #pragma unroll
    for (int u = 0; u < 8; u++)
        dstn[u] = sb + OFF_T0 + (1 + gst) * 2048 + SWZ((uint32_t)(rstn * 128 + u * 16));

    // ---- MMA per-lane ldmatrix geometry ----
    const int mid   = lane >> 3;                              // matrix id 0..3
    const int lrow  = (lane & 7) + ((mid & 1) << 3);          // source row 0..15
    const int c16   = (mid >> 1) << 4;                        // k-chunk byte offset
    const uint32_t xr = (uint32_t)((lrow & 7) * 16);
    const uint32_t rowoff = (uint32_t)(lrow * 128);
    uint32_t kso[4];
    #pragma unroll
    for (int ks = 0; ks < 4; ks++)
        kso[ks] = ((uint32_t)(ks * 32 + c16)) ^ xr;

    // ---- prologue: stage tile0 into buf0; prefetch idx for tile1 ----
    int tile = blockIdx.x;
    {
        const int p = tile * TILE + rstn;
        int idx = -1;
        if (tile < ntiles && p < n)
            idx = isnext ? __ldg(&nbr_next[ast * n + p]) : __ldg(&nbr_prev[ast * n + p]);
        if (tile < ntiles) {
            const int pbase = tile * TILE;
            { const int pc = pbase + rc0;
              cp16(sb + dstc0, &f4[(long)(pc < n ? pc : 0) * 8 + uc0], pc < n ? 16u : 0u); }
            if (c1v) { const int pc = pbase + rc1;
              cp16(sb + dstc1, &f4[(long)(pc < n ? pc : 0) * 8 + uc1], pc < n ? 16u : 0u); }
            cp16x8(dstn[0], dstn[1], dstn[2], dstn[3], dstn[4], dstn[5], dstn[6], dstn[7],
                   &f4[(long)(idx >= 0 ? idx : 0) * 8], (idx >= 0) ? 16u : 0u);
        }
        asm volatile("cp.async.commit_group;" ::: "memory");
    }
    int pidx1;
    {
        const int t1 = tile + grid;
        const int p = t1 * TILE + rstn;
        pidx1 = -1;
        if (t1 < ntiles && p < n)
            pidx1 = isnext ? __ldg(&nbr_next[ast * n + p]) : __ldg(&nbr_prev[ast * n + p]);
    }

    int cur = 0;
    for (; tile < ntiles; tile += grid) {
        asm volatile("cp.async.wait_group 0;" ::: "memory");
        __syncthreads();
        const uint32_t bufadd = cur ? (uint32_t)DBUF : 0u;
        const uint32_t tb = sb + OFF_T0 + bufadd;
        const int pbase = tile * TILE;
        const int ntile = tile + grid;

        // ---- stage tile t+1 NOW (latency covered by MMA+epilogue below) ----
        if (ntile < ntiles) {
            const uint32_t oadd = cur ? 0u : (uint32_t)DBUF;
            const int npb = ntile * TILE;
            { const int pc = npb + rc0;
              cp16(sb + dstc0 + oadd, &f4[(long)(pc < n ? pc : 0) * 8 + uc0], pc < n ? 16u : 0u); }
            if (c1v) { const int pc = npb + rc1;
              cp16(sb + dstc1 + oadd, &f4[(long)(pc < n ? pc : 0) * 8 + uc1], pc < n ? 16u : 0u); }
            cp16x8(dstn[0] + oadd, dstn[1] + oadd, dstn[2] + oadd, dstn[3] + oadd,
                   dstn[4] + oadd, dstn[5] + oadd, dstn[6] + oadd, dstn[7] + oadd,
                   &f4[(long)(pidx1 >= 0 ? pidx1 : 0) * 8], (pidx1 >= 0) ? 16u : 0u);
        }
        asm volatile("cp.async.commit_group;" ::: "memory");

        // ---- prefetch idx for tile t+2 (LDG covered by MMA) ----
        int pidx2 = -1;
        {
            const int t2 = ntile + grid;
            const int p = t2 * TILE + rstn;
            if (t2 < ntiles && p < n)
                pidx2 = isnext ? __ldg(&nbr_next[ast * n + p]) : __ldg(&nbr_prev[ast * n + p]);
        }

        // per-tap A bases with lane row folded in
        uint32_t gbs[3];
        gbs[0] = tb + (1 + 2 * br) * 2048 + rowoff;
        gbs[1] = tb + rowoff;
        gbs[2] = tb + (2 + 2 * br) * 2048 + rowoff;

        float acc[4][4];
        #pragma unroll
        for (int nc = 0; nc < 4; nc++) {
            const float2 b2 = *(const float2*)&biasm[br * 32 + 8 * nc + 2 * (lane & 3)];
            acc[nc][0] = acc[nc][2] = b2.x;
            acc[nc][1] = acc[nc][3] = b2.y;
        }

        // ---- software-pipelined 12-step MMA loop (ldmatrix.x4 A-frags) ----
        uint32_t af[2][4];
        ldsm4(af[0], gbs[0] + kso[0]);
        #pragma unroll
        for (int s = 0; s < 12; s++) {
            const int pb = s & 1;
            if (s < 11) {
                const int s1s = s + 1;
                ldsm4(af[pb ^ 1], gbs[s1s >> 2] + kso[s1s & 3]);
            }
            const int t = s >> 2, ks = s & 3;
            #pragma unroll
            for (int nc = 0; nc < 4; nc++)
                mma_tf32(acc[nc], af[pb][0], af[pb][1], af[pb][2], af[pb][3],
                         breg[t][ks][nc][0], breg[t][ks][nc][1]);
        }

        // ---- sigmoid + partial store (stride-40 reduction buffer) ----
        #pragma unroll
        for (int nc = 0; nc < 4; nc++)
            #pragma unroll
            for (int rr = 0; rr < 2; rr++) {
                const int rowp = (lane >> 2) + 8 * rr;
                const uint32_t addr = sb + OFF_R +
                    (((br * 16 + rowp) * RSTRIDE + 8 * nc + 2 * (lane & 3)) << 2);
                asm volatile("st.shared.v2.f32 [%0], {%1, %2};"
                             :: "r"(addr), "f"(sigmoid_fast(acc[nc][2 * rr])),
                                "f"(sigmoid_fast(acc[nc][2 * rr + 1])) : "memory");
            }
        __syncthreads();

        // ---- epilogue: sum 3 branches, gate by exact fp32 x, store ----
        #pragma unroll
        for (int k = 0; k < 2; k++) {
            const int s = tid + k * TPB;
            if (s < 128) {
                const int row = s >> 3, q = s & 7;
                const uint32_t rb = sb + OFF_R + ((row * RSTRIDE + 4 * q) << 2);
                const float4 s0 = lds128f(rb);
                const float4 s1v = lds128f(rb + 16 * RSTRIDE * 4);
                const float4 s2 = lds128f(rb + 32 * RSTRIDE * 4);
                const float4 x  = lds128f(tb + SWZ((uint32_t)(row * 128 + q * 16)));
                const int p = pbase + row;
                if (p < n) {
                    float4 v;
                    v.x = (s0.x + s1v.x + s2.x) * x.x;
                    v.y = (s0.y + s1v.y + s2.y) * x.y;
                    v.z = (s0.z + s1v.z + s2.z) * x.z;
                    v.w = (s0.w + s1v.w + s2.w) * x.w;
                    ((float4*)out)[(long)p * 8 + q] = v;
                }
            }
        }
        pidx1 = pidx2;
        cur ^= 1;
    }
}

extern "C" void kernel_launch(void* const* d_in, const int* in_sizes, int n_in,
                              void* d_out, int out_size) {
    const float* f     = (const float*)d_in[0];
    const int*   nprev = (const int*)  d_in[1];
    const int*   nnext = (const int*)  d_in[2];
    const float* W     = (const float*)d_in[3];
    const float* gamma = (const float*)d_in[4];
    const float* beta  = (const float*)d_in[5];
    const float* mean  = (const float*)d_in[6];
    const float* var   = (const float*)d_in[7];
    const int n = in_sizes[0] / 32;

    cudaFuncSetAttribute(recon_kernel, cudaFuncAttributeMaxDynamicSharedMemorySize,
                         SMEM_TOTAL);
    recon_kernel<<<592, TPB, SMEM_TOTAL>>>(f, nprev, nnext, W, gamma, beta, mean, var,
                                           (float*)d_out, n);
}